// round 2
// baseline (speedup 1.0000x reference)
#include <cuda_runtime.h>
#include <cuda_bf16.h>
#include <cstdint>

#define HIDDEN 128
#define MAX_NODES 50048
#define MAX_EDGES 800000

// ---------------- scratch (static device globals; no allocation) -------------
__device__ float g_agg[(size_t)MAX_NODES * HIDDEN];
__device__ float g_h  [(size_t)MAX_NODES * HIDDEN];
__device__ float g_colsum[HIDDEN];
__device__ float g_b1eff[HIDDEN];

// ---------------- kernel 1: zero agg + colsum -------------------------------
__global__ void zero_kernel(int n_nodes) {
    size_t total = (size_t)n_nodes * HIDDEN;
    size_t i = (size_t)blockIdx.x * blockDim.x + threadIdx.x;
    size_t stride = (size_t)gridDim.x * blockDim.x;
    for (size_t idx = i; idx < total; idx += stride) g_agg[idx] = 0.0f;
    if (i < HIDDEN) g_colsum[i] = 0.0f;
}

// ---------------- kernel 2: scatter-add + edge_attr passthrough -------------
// one warp per edge: 32 lanes x float4 = 128 floats. IDX = int or long long.
template<typename IDX>
__global__ void scatter_copy_kernel(const float4* __restrict__ ea,
                                    const IDX* __restrict__ recv,
                                    float4* __restrict__ out_ea,   // may be null
                                    int n_edges) {
    int warp = (int)(((size_t)blockIdx.x * blockDim.x + threadIdx.x) >> 5);
    int lane = threadIdx.x & 31;
    if (warp >= n_edges) return;
    int r = (int)__ldg(&recv[warp]);
    float4 v = __ldg(&ea[(size_t)warp * 32 + lane]);
    if (out_ea) out_ea[(size_t)warp * 32 + lane] = v;
    float* dst = g_agg + (size_t)r * HIDDEN + lane * 4;
    asm volatile("red.global.add.v4.f32 [%0], {%1,%2,%3,%4};"
                 :: "l"(dst), "f"(v.x), "f"(v.y), "f"(v.z), "f"(v.w)
                 : "memory");
}

// ---------------- kernel 3: edge_index passthrough ---------------------------
__global__ void ei_copy_i32_as_float_kernel(const int* __restrict__ ei,
                                            float* __restrict__ out, int n) {
    int i = blockIdx.x * blockDim.x + threadIdx.x;
    if (i < n) out[i] = (float)ei[i];
}
__global__ void ei_copy_raw64_kernel(const long long* __restrict__ ei,
                                     long long* __restrict__ out, int n) {
    int i = blockIdx.x * blockDim.x + threadIdx.x;
    if (i < n) out[i] = ei[i];
}

// ---------------- kernel 4: column sums of agg -------------------------------
__global__ void colsum_kernel(int n_nodes) {
    int col = threadIdx.x;             // blockDim.x == 128
    float s = 0.0f;
    for (int r = blockIdx.x; r < n_nodes; r += gridDim.x)
        s += g_agg[(size_t)r * HIDDEN + col];
    atomicAdd(&g_colsum[col], s);
}

// ---------------- kernel 5: fold mean into bias ------------------------------
// b1_eff[j] = b1[j] - sum_k mean[k] * W1[(128+k)*128 + j]
__global__ void b1eff_kernel(const float* __restrict__ W1,
                             const float* __restrict__ b1, int n_nodes) {
    int j = threadIdx.x;               // 128 threads
    float inv = 1.0f / (float)n_nodes;
    float s = b1[j];
    #pragma unroll 8
    for (int k = 0; k < HIDDEN; k++)
        s -= g_colsum[k] * inv * W1[(size_t)(HIDDEN + k) * HIDDEN + j];
    g_b1eff[j] = s;
}

// ---------------- kernels 6/7: tiled FP32 GEMM -------------------------------
// C[M x 128] = A[M x KTOT] @ W[KTOT x 128] (+ bias, optional relu)
// A is a virtual concat: k < 128 -> A0, k >= 128 -> A1 (both [M x 128]).
// Block: 256 threads, TILE_M = 64 rows, full N = 128. 4x8 register micro-tile.
#define TM 64
template<int KTOT, bool RELU>
__global__ void gemm_kernel(const float* __restrict__ A0,
                            const float* __restrict__ A1,
                            const float* __restrict__ W,
                            const float* __restrict__ bias,
                            float* __restrict__ out, int n_rows) {
    __shared__ float As[16][TM];        // transposed: As[k][m]
    __shared__ float Bs[16][HIDDEN];

    int tid = threadIdx.x;              // 0..255
    int tn  = tid & 15;                 // 16 threads over N (8 cols each)
    int tm  = tid >> 4;                 // 16 threads over M (4 rows each)
    int row0 = blockIdx.x * TM;

    float acc[4][8];
    #pragma unroll
    for (int i = 0; i < 4; i++)
        #pragma unroll
        for (int j = 0; j < 8; j++) acc[i][j] = 0.0f;

    for (int k0 = 0; k0 < KTOT; k0 += 16) {
        const float* Asrc = (KTOT > HIDDEN && k0 >= HIDDEN) ? A1 : A0;
        int kbase = (KTOT > HIDDEN && k0 >= HIDDEN) ? (k0 - HIDDEN) : k0;

        // stage A tile (64 x 16), store transposed
        {
            int r = tid >> 2;             // 0..63
            int c = (tid & 3) * 4;        // 0,4,8,12
            int grow = row0 + r;
            float4 v = (grow < n_rows)
                ? *(const float4*)&Asrc[(size_t)grow * HIDDEN + kbase + c]
                : make_float4(0.f, 0.f, 0.f, 0.f);
            As[c + 0][r] = v.x; As[c + 1][r] = v.y;
            As[c + 2][r] = v.z; As[c + 3][r] = v.w;
        }
        // stage B tile (16 x 128) = 512 float4, 2 per thread
        {
            #pragma unroll
            for (int t = 0; t < 2; t++) {
                int f  = tid + t * 256;   // 0..511
                int br = f >> 5;          // 0..15
                int bc = (f & 31) * 4;    // 0..124
                *(float4*)&Bs[br][bc] =
                    *(const float4*)&W[(size_t)(k0 + br) * HIDDEN + bc];
            }
        }
        __syncthreads();

        #pragma unroll
        for (int kk = 0; kk < 16; kk++) {
            float a[4], b[8];
            *(float4*)a       = *(const float4*)&As[kk][tm * 4];
            *(float4*)b       = *(const float4*)&Bs[kk][tn * 8];
            *(float4*)(b + 4) = *(const float4*)&Bs[kk][tn * 8 + 4];
            #pragma unroll
            for (int i = 0; i < 4; i++)
                #pragma unroll
                for (int j = 0; j < 8; j++)
                    acc[i][j] += a[i] * b[j];
        }
        __syncthreads();
    }

    // epilogue
    float bv[8];
    #pragma unroll
    for (int j = 0; j < 8; j++) bv[j] = bias[tn * 8 + j];
    #pragma unroll
    for (int i = 0; i < 4; i++) {
        int grow = row0 + tm * 4 + i;
        if (grow < n_rows) {
            float o[8];
            #pragma unroll
            for (int j = 0; j < 8; j++) {
                float v = acc[i][j] + bv[j];
                o[j] = RELU ? fmaxf(v, 0.0f) : v;
            }
            float* dst = &out[(size_t)grow * HIDDEN + tn * 8];
            *(float4*)dst       = *(float4*)o;
            *(float4*)(dst + 4) = *(float4*)(o + 4);
        }
    }
}

// ---------------- launcher ---------------------------------------------------
extern "C" void kernel_launch(void* const* d_in, const int* in_sizes, int n_in,
                              void* d_out, int out_size) {
    const float* node_attr = (const float*)d_in[0];
    const void*  edge_index = d_in[1];           // dtype resolved below
    const float* edge_attr  = (const float*)d_in[2];
    const float* W1         = (const float*)d_in[3];
    const float* b1         = (const float*)d_in[4];
    const float* W2         = (const float*)d_in[5];
    const float* b2         = (const float*)d_in[6];

    int n_nodes = in_sizes[0] / HIDDEN;
    int n_edges = in_sizes[1] / 2;

    size_t x_el  = (size_t)n_nodes * HIDDEN;
    size_t ei_el = 2 * (size_t)n_edges;
    size_t ea_el = (size_t)n_edges * HIDDEN;

    float* out   = (float*)d_out;
    float* out_x = out;

    // Resolve output layout AND index dtype from out_size:
    //   x + ei + ea         -> 4-byte indices (int32), ei cast to float
    //   x + 2*ei + ea       -> 8-byte indices (int64), ei passed raw
    //   x only              -> indices int32 (JAX default x64-disabled)
    size_t os = (size_t)out_size;
    bool idx64 = false;
    float*     out_ei_f   = nullptr;
    long long* out_ei_raw = nullptr;
    float*     out_ea     = nullptr;
    if (os == x_el + ei_el + ea_el) {
        idx64 = false;
        out_ei_f = out + x_el;
        out_ea   = out + x_el + ei_el;
    } else if (os == x_el + 2 * ei_el + ea_el) {
        idx64 = true;
        out_ei_raw = (long long*)(out + x_el);
        out_ea     = out + x_el + 2 * ei_el;
    }

    float* d_agg;   cudaGetSymbolAddress((void**)&d_agg, g_agg);
    float* d_h;     cudaGetSymbolAddress((void**)&d_h,   g_h);
    float* d_b1eff; cudaGetSymbolAddress((void**)&d_b1eff, g_b1eff);

    // 1. zero agg (+ colsum)
    {
        size_t total = (size_t)n_nodes * HIDDEN;
        int blocks = (int)((total + 511) / 512);
        if (blocks > 4096) blocks = 4096;
        zero_kernel<<<blocks, 512>>>(n_nodes);
    }

    // 2. scatter + edge_attr passthrough (one warp per edge)
    {
        long long total_threads = (long long)n_edges * 32;
        int blocks = (int)((total_threads + 255) / 256);
        if (idx64) {
            const long long* recv = (const long long*)edge_index + n_edges;
            scatter_copy_kernel<long long><<<blocks, 256>>>(
                (const float4*)edge_attr, recv, (float4*)out_ea, n_edges);
        } else {
            const int* recv = (const int*)edge_index + n_edges;
            scatter_copy_kernel<int><<<blocks, 256>>>(
                (const float4*)edge_attr, recv, (float4*)out_ea, n_edges);
        }
    }

    // 3. edge_index passthrough
    if (out_ei_f) {
        int n = 2 * n_edges;
        ei_copy_i32_as_float_kernel<<<(n + 255) / 256, 256>>>(
            (const int*)edge_index, out_ei_f, n);
    } else if (out_ei_raw) {
        int n = 2 * n_edges;
        ei_copy_raw64_kernel<<<(n + 255) / 256, 256>>>(
            (const long long*)edge_index, out_ei_raw, n);
    }

    // 4. column sums of agg
    colsum_kernel<<<512, HIDDEN>>>(n_nodes);

    // 5. fold column means into bias
    b1eff_kernel<<<1, HIDDEN>>>(W1, b1, n_nodes);

    // 6. layer 1: h = relu([node|agg] @ W1 + b1_eff)
    {
        int blocks = (n_nodes + TM - 1) / TM;
        gemm_kernel<256, true><<<blocks, 256>>>(node_attr, d_agg, W1,
                                                d_b1eff, d_h, n_nodes);
    }

    // 7. layer 2: x = h @ W2 + b2
    {
        int blocks = (n_nodes + TM - 1) / TM;
        gemm_kernel<128, false><<<blocks, 256>>>(d_h, nullptr, W2,
                                                 b2, out_x, n_nodes);
    }
}

// round 4
// speedup vs baseline: 1.4947x; 1.4947x over previous
#include <cuda_runtime.h>
#include <cuda_bf16.h>
#include <cstdint>

#define HIDDEN 128
#define MAX_NODES 50048
#define MAX_EDGES 800000

// ---------------- scratch (static device globals; no allocation) -------------
__device__ float g_agg[(size_t)MAX_NODES * HIDDEN];
__device__ float g_h  [(size_t)MAX_NODES * HIDDEN];
__device__ float g_colsum[HIDDEN];
__device__ float g_b1eff[HIDDEN];

// ---------------- kernel 1: zero agg + colsum -------------------------------
__global__ void zero_kernel(int n_nodes) {
    size_t total = (size_t)n_nodes * HIDDEN;
    size_t i = (size_t)blockIdx.x * blockDim.x + threadIdx.x;
    size_t stride = (size_t)gridDim.x * blockDim.x;
    for (size_t idx = i; idx < total; idx += stride) g_agg[idx] = 0.0f;
    if (i < HIDDEN) g_colsum[i] = 0.0f;
}

// ---------------- kernel 2: scatter-add + edge_attr copy + colsum ------------
// grid-stride, one warp per edge per iteration. Column sums of agg ==
// column sums of edge_attr (every edge hits exactly one receiver), so we
// accumulate them here in registers and flush once per block.
template<typename IDX>
__global__ void scatter_copy_kernel(const float4* __restrict__ ea,
                                    const IDX* __restrict__ recv,
                                    float4* __restrict__ out_ea,   // may be null
                                    int n_edges) {
    int wl   = threadIdx.x >> 5;           // warp in block (0..7)
    int lane = threadIdx.x & 31;
    int gw   = blockIdx.x * 8 + wl;
    int nW   = gridDim.x * 8;

    float4 acc = make_float4(0.f, 0.f, 0.f, 0.f);
    for (int e = gw; e < n_edges; e += nW) {
        int r = (int)__ldg(&recv[e]);
        float4 v = __ldg(&ea[(size_t)e * 32 + lane]);
        if (out_ea) out_ea[(size_t)e * 32 + lane] = v;
        acc.x += v.x; acc.y += v.y; acc.z += v.z; acc.w += v.w;
        float* dst = g_agg + (size_t)r * HIDDEN + lane * 4;
        asm volatile("red.global.add.v4.f32 [%0], {%1,%2,%3,%4};"
                     :: "l"(dst), "f"(v.x), "f"(v.y), "f"(v.z), "f"(v.w)
                     : "memory");
    }

    __shared__ float4 reds[8][32];
    reds[wl][lane] = acc;
    __syncthreads();
    if (wl == 0) {
        float4 s = reds[0][lane];
        #pragma unroll
        for (int w = 1; w < 8; w++) {
            float4 t = reds[w][lane];
            s.x += t.x; s.y += t.y; s.z += t.z; s.w += t.w;
        }
        atomicAdd(&g_colsum[lane * 4 + 0], s.x);
        atomicAdd(&g_colsum[lane * 4 + 1], s.y);
        atomicAdd(&g_colsum[lane * 4 + 2], s.z);
        atomicAdd(&g_colsum[lane * 4 + 3], s.w);
    }
}

// ---------------- kernel 3: edge_index passthrough ---------------------------
__global__ void ei_copy_i32_as_float_kernel(const int* __restrict__ ei,
                                            float* __restrict__ out, int n) {
    int i = blockIdx.x * blockDim.x + threadIdx.x;
    if (i < n) out[i] = (float)ei[i];
}
__global__ void ei_copy_raw64_kernel(const long long* __restrict__ ei,
                                     long long* __restrict__ out, int n) {
    int i = blockIdx.x * blockDim.x + threadIdx.x;
    if (i < n) out[i] = ei[i];
}

// ---------------- kernel 4: fold mean into bias ------------------------------
__global__ void b1eff_kernel(const float* __restrict__ W1,
                             const float* __restrict__ b1, int n_nodes) {
    int j = threadIdx.x;               // 128 threads
    float inv = 1.0f / (float)n_nodes;
    float s = b1[j];
    #pragma unroll 8
    for (int k = 0; k < HIDDEN; k++)
        s -= g_colsum[k] * inv * W1[(size_t)(HIDDEN + k) * HIDDEN + j];
    g_b1eff[j] = s;
}

// ---------------- tf32 tensor-core GEMM --------------------------------------
// C[M x 128] = A[M x KTOT] @ W[KTOT x 128] (+bias, optional relu)
// A virtual concat: k<128 -> A0, k>=128 -> A1.
// Block: 256 threads = 8 warps (2 M-warps x 4 N-warps). Block tile 128x128.
// Warp tile 64x32. k-tile 32, mma.sync m16n8k8 tf32.
// smem k-permutation p(k) = (k&3)*8 + (k>>2); row pad 37 words (odd) keeps
// all fragment-load lanes on distinct banks. All smem fragment loads are
// 32-bit (SPAD odd => 64-bit loads would be misaligned).
#define SPAD 37

__device__ __forceinline__ uint32_t f2tf32(float f) {
    uint32_t u;
    asm("cvt.rna.tf32.f32 %0, %1;" : "=r"(u) : "f"(f));
    return u;
}

template<int KTOT, bool RELU>
__global__ void __launch_bounds__(256)
gemm_tc_kernel(const float* __restrict__ A0,
               const float* __restrict__ A1,
               const float* __restrict__ W,
               const float* __restrict__ bias,
               float* __restrict__ out, int n_rows) {
    __shared__ uint32_t As[128 * SPAD];
    __shared__ uint32_t Bs[128 * SPAD];
    __shared__ float    sBias[HIDDEN];

    int tid  = threadIdx.x;
    int lane = tid & 31;
    int wid  = tid >> 5;
    int q    = lane & 3;
    int lg   = lane >> 2;          // lane group 0..7
    int wm   = wid >> 2;           // 0..1 : warp row (64 rows each)
    int wn   = wid & 3;            // 0..3 : warp col (32 cols each)
    int Rw   = wm * 64;
    int Nw   = wn * 32;
    int row0 = blockIdx.x * 128;

    if (tid < HIDDEN) sBias[tid] = bias[tid];

    float c[4][4][4];              // [m-tile][n-tile][frag]
    #pragma unroll
    for (int i = 0; i < 4; i++)
        #pragma unroll
        for (int j = 0; j < 4; j++)
            #pragma unroll
            for (int t = 0; t < 4; t++) c[i][j][t] = 0.0f;

    for (int k0 = 0; k0 < KTOT; k0 += 32) {
        const float* Asrc = (KTOT > HIDDEN && k0 >= HIDDEN) ? A1 : A0;
        int kb = (KTOT > HIDDEN && k0 >= HIDDEN) ? (k0 - HIDDEN) : k0;

        // stage A: 128 rows x 32 k, float4 loads, k-permuted stores
        #pragma unroll
        for (int it = 0; it < 4; it++) {
            int idx = tid + it * 256;      // 0..1023
            int row = idx >> 3;
            int t   = idx & 7;             // float4 index along k
            int grow = row0 + row;
            float4 v = (grow < n_rows)
                ? __ldg((const float4*)&Asrc[(size_t)grow * HIDDEN + kb + t * 4])
                : make_float4(0.f, 0.f, 0.f, 0.f);
            uint32_t* dst = &As[row * SPAD + t];   // p(4t+j) = j*8 + t
            dst[0]  = f2tf32(v.x);
            dst[8]  = f2tf32(v.y);
            dst[16] = f2tf32(v.z);
            dst[24] = f2tf32(v.w);
        }
        // stage B: W rows k0..k0+31, transposed to Bs[n][p(k)]
        {
            int n    = tid & 127;
            int koff = (tid >> 7) * 16;
            #pragma unroll
            for (int u = 0; u < 16; u++) {
                int k = koff + u;
                float bv = __ldg(&W[(size_t)(k0 + k) * HIDDEN + n]);
                Bs[n * SPAD + (k & 3) * 8 + (k >> 2)] = f2tf32(bv);
            }
        }
        __syncthreads();

        #pragma unroll
        for (int s = 0; s < 4; s++) {
            uint32_t a[4][4];
            #pragma unroll
            for (int mt = 0; mt < 4; mt++) {
                int r = Rw + mt * 16 + lg;
                int o0 = r * SPAD + q * 8 + 2 * s;
                int o1 = (r + 8) * SPAD + q * 8 + 2 * s;
                a[mt][0] = As[o0];      // (r,   k)
                a[mt][2] = As[o0 + 1];  // (r,   k+4)
                a[mt][1] = As[o1];      // (r+8, k)
                a[mt][3] = As[o1 + 1];  // (r+8, k+4)
            }
            uint32_t b[4][2];
            #pragma unroll
            for (int nt = 0; nt < 4; nt++) {
                int ob = (Nw + nt * 8 + lg) * SPAD + q * 8 + 2 * s;
                b[nt][0] = Bs[ob];
                b[nt][1] = Bs[ob + 1];
            }
            #pragma unroll
            for (int mt = 0; mt < 4; mt++)
                #pragma unroll
                for (int nt = 0; nt < 4; nt++) {
                    asm volatile(
                        "mma.sync.aligned.m16n8k8.row.col.f32.tf32.tf32.f32 "
                        "{%0,%1,%2,%3}, {%4,%5,%6,%7}, {%8,%9}, {%0,%1,%2,%3};"
                        : "+f"(c[mt][nt][0]), "+f"(c[mt][nt][1]),
                          "+f"(c[mt][nt][2]), "+f"(c[mt][nt][3])
                        : "r"(a[mt][0]), "r"(a[mt][1]),
                          "r"(a[mt][2]), "r"(a[mt][3]),
                          "r"(b[nt][0]), "r"(b[nt][1]));
                }
        }
        __syncthreads();
    }

    // epilogue: bias (+relu), direct STG.64
    #pragma unroll
    for (int mt = 0; mt < 4; mt++) {
        int r0g = row0 + Rw + mt * 16 + lg;
        int r1g = r0g + 8;
        #pragma unroll
        for (int nt = 0; nt < 4; nt++) {
            int col = Nw + nt * 8 + 2 * q;
            float b0 = sBias[col], b1v = sBias[col + 1];
            float v0 = c[mt][nt][0] + b0, v1 = c[mt][nt][1] + b1v;
            float v2 = c[mt][nt][2] + b0, v3 = c[mt][nt][3] + b1v;
            if (RELU) {
                v0 = fmaxf(v0, 0.f); v1 = fmaxf(v1, 0.f);
                v2 = fmaxf(v2, 0.f); v3 = fmaxf(v3, 0.f);
            }
            if (r0g < n_rows)
                *(float2*)&out[(size_t)r0g * HIDDEN + col] = make_float2(v0, v1);
            if (r1g < n_rows)
                *(float2*)&out[(size_t)r1g * HIDDEN + col] = make_float2(v2, v3);
        }
    }
}

// ---------------- launcher ---------------------------------------------------
extern "C" void kernel_launch(void* const* d_in, const int* in_sizes, int n_in,
                              void* d_out, int out_size) {
    const float* node_attr  = (const float*)d_in[0];
    const void*  edge_index = d_in[1];
    const float* edge_attr  = (const float*)d_in[2];
    const float* W1         = (const float*)d_in[3];
    const float* b1         = (const float*)d_in[4];
    const float* W2         = (const float*)d_in[5];
    const float* b2         = (const float*)d_in[6];

    int n_nodes = in_sizes[0] / HIDDEN;
    int n_edges = in_sizes[1] / 2;

    size_t x_el  = (size_t)n_nodes * HIDDEN;
    size_t ei_el = 2 * (size_t)n_edges;
    size_t ea_el = (size_t)n_edges * HIDDEN;

    float* out   = (float*)d_out;
    float* out_x = out;

    size_t os = (size_t)out_size;
    bool idx64 = false;
    float*     out_ei_f   = nullptr;
    long long* out_ei_raw = nullptr;
    float*     out_ea     = nullptr;
    if (os == x_el + ei_el + ea_el) {
        idx64 = false;
        out_ei_f = out + x_el;
        out_ea   = out + x_el + ei_el;
    } else if (os == x_el + 2 * ei_el + ea_el) {
        idx64 = true;
        out_ei_raw = (long long*)(out + x_el);
        out_ea     = out + x_el + 2 * ei_el;
    }

    float* d_agg;   cudaGetSymbolAddress((void**)&d_agg, g_agg);
    float* d_h;     cudaGetSymbolAddress((void**)&d_h,   g_h);
    float* d_b1eff; cudaGetSymbolAddress((void**)&d_b1eff, g_b1eff);

    // 1. zero agg + colsum
    {
        size_t total = (size_t)n_nodes * HIDDEN;
        int blocks = (int)((total + 511) / 512);
        if (blocks > 4096) blocks = 4096;
        zero_kernel<<<blocks, 512>>>(n_nodes);
    }

    // 2. scatter + edge_attr copy + colsum (grid-stride, warp per edge)
    {
        int blocks = 2048;
        if (idx64) {
            const long long* recv = (const long long*)edge_index + n_edges;
            scatter_copy_kernel<long long><<<blocks, 256>>>(
                (const float4*)edge_attr, recv, (float4*)out_ea, n_edges);
        } else {
            const int* recv = (const int*)edge_index + n_edges;
            scatter_copy_kernel<int><<<blocks, 256>>>(
                (const float4*)edge_attr, recv, (float4*)out_ea, n_edges);
        }
    }

    // 3. edge_index passthrough
    if (out_ei_f) {
        int n = 2 * n_edges;
        ei_copy_i32_as_float_kernel<<<(n + 255) / 256, 256>>>(
            (const int*)edge_index, out_ei_f, n);
    } else if (out_ei_raw) {
        int n = 2 * n_edges;
        ei_copy_raw64_kernel<<<(n + 255) / 256, 256>>>(
            (const long long*)edge_index, out_ei_raw, n);
    }

    // 4. fold column means into bias
    b1eff_kernel<<<1, HIDDEN>>>(W1, b1, n_nodes);

    // 5. layer 1: h = relu([node|agg] @ W1 + b1_eff)   (tf32 tensor cores)
    {
        int blocks = (n_nodes + 127) / 128;
        gemm_tc_kernel<256, true><<<blocks, 256>>>(node_attr, d_agg, W1,
                                                   d_b1eff, d_h, n_nodes);
    }

    // 6. layer 2: x = h @ W2 + b2
    {
        int blocks = (n_nodes + 127) / 128;
        gemm_tc_kernel<128, false><<<blocks, 256>>>(d_h, nullptr, W2,
                                                    b2, out_x, n_nodes);
    }
}

// round 5
// speedup vs baseline: 1.4968x; 1.0014x over previous
#include <cuda_runtime.h>
#include <cuda_bf16.h>
#include <cstdint>

#define HIDDEN 128
#define MAX_NODES 50048
#define MAX_EDGES 800000

// ---------------- scratch (static device globals; no allocation) -------------
__device__ float g_agg[(size_t)MAX_NODES * HIDDEN];
__device__ float g_colsum[HIDDEN];
__device__ float g_b1eff[HIDDEN];

// ---------------- kernel 1: zero agg + colsum -------------------------------
__global__ void zero_kernel(int n_nodes) {
    size_t total = (size_t)n_nodes * HIDDEN;
    size_t i = (size_t)blockIdx.x * blockDim.x + threadIdx.x;
    size_t stride = (size_t)gridDim.x * blockDim.x;
    for (size_t idx = i; idx < total; idx += stride) g_agg[idx] = 0.0f;
    if (i < HIDDEN) g_colsum[i] = 0.0f;
}

// ---------------- kernel 2: scatter-add + edge_attr copy + colsum ------------
template<typename IDX>
__global__ void scatter_copy_kernel(const float4* __restrict__ ea,
                                    const IDX* __restrict__ recv,
                                    float4* __restrict__ out_ea,   // may be null
                                    int n_edges) {
    int wl   = threadIdx.x >> 5;
    int lane = threadIdx.x & 31;
    int gw   = blockIdx.x * 8 + wl;
    int nW   = gridDim.x * 8;

    float4 acc = make_float4(0.f, 0.f, 0.f, 0.f);
    for (int e = gw; e < n_edges; e += nW) {
        int r = (int)__ldg(&recv[e]);
        float4 v = __ldg(&ea[(size_t)e * 32 + lane]);
        if (out_ea) out_ea[(size_t)e * 32 + lane] = v;
        acc.x += v.x; acc.y += v.y; acc.z += v.z; acc.w += v.w;
        float* dst = g_agg + (size_t)r * HIDDEN + lane * 4;
        asm volatile("red.global.add.v4.f32 [%0], {%1,%2,%3,%4};"
                     :: "l"(dst), "f"(v.x), "f"(v.y), "f"(v.z), "f"(v.w)
                     : "memory");
    }

    __shared__ float4 reds[8][32];
    reds[wl][lane] = acc;
    __syncthreads();
    if (wl == 0) {
        float4 s = reds[0][lane];
        #pragma unroll
        for (int w = 1; w < 8; w++) {
            float4 t = reds[w][lane];
            s.x += t.x; s.y += t.y; s.z += t.z; s.w += t.w;
        }
        atomicAdd(&g_colsum[lane * 4 + 0], s.x);
        atomicAdd(&g_colsum[lane * 4 + 1], s.y);
        atomicAdd(&g_colsum[lane * 4 + 2], s.z);
        atomicAdd(&g_colsum[lane * 4 + 3], s.w);
    }
}

// ---------------- kernel 3: edge_index passthrough ---------------------------
__global__ void ei_copy_i32_as_float_kernel(const int* __restrict__ ei,
                                            float* __restrict__ out, int n) {
    int i = blockIdx.x * blockDim.x + threadIdx.x;
    if (i < n) out[i] = (float)ei[i];
}
__global__ void ei_copy_raw64_kernel(const long long* __restrict__ ei,
                                     long long* __restrict__ out, int n) {
    int i = blockIdx.x * blockDim.x + threadIdx.x;
    if (i < n) out[i] = ei[i];
}

// ---------------- kernel 4: fold mean into bias (parallel) -------------------
// block j computes b1eff[j] = b1[j] - sum_k colsum[k]/n * W1[(128+k)*128 + j]
__global__ void b1eff_kernel(const float* __restrict__ W1,
                             const float* __restrict__ b1, int n_nodes) {
    int j = blockIdx.x;
    int k = threadIdx.x;               // 128 threads
    float inv = 1.0f / (float)n_nodes;
    float v = g_colsum[k] * inv * __ldg(&W1[(size_t)(HIDDEN + k) * HIDDEN + j]);
    // warp + smem reduce (128 -> 1)
    #pragma unroll
    for (int o = 16; o > 0; o >>= 1) v += __shfl_down_sync(0xffffffffu, v, o);
    __shared__ float red[4];
    if ((k & 31) == 0) red[k >> 5] = v;
    __syncthreads();
    if (k == 0)
        g_b1eff[j] = b1[j] - (red[0] + red[1] + red[2] + red[3]);
}

// ---------------- fused 2-layer tf32 tensor-core MLP -------------------------
// Per 128-row block:
//   h  = relu([node|agg] @ W1 + b1eff)   (K=256, kept in registers)
//   x  = h @ W2 + b2                     (h re-staged through smem, K=128)
// 256 threads = 8 warps (2 M x 4 N). Warp tile 64x32. mma m16n8k8 tf32.
// smem k-permutation p(k) = (k&3)*8 + (k>>2); SPAD=37 (odd) -> conflict-free,
// all fragment accesses 32-bit.
#define SPAD 37

__device__ __forceinline__ uint32_t f2tf32(float f) {
    uint32_t u;
    asm("cvt.rna.tf32.f32 %0, %1;" : "=r"(u) : "f"(f));
    return u;
}

__global__ void __launch_bounds__(256)
fused_mlp_kernel(const float* __restrict__ A0,   // node_attr
                 const float* __restrict__ A1,   // agg
                 const float* __restrict__ W1,
                 const float* __restrict__ W2,
                 const float* __restrict__ b2,
                 float* __restrict__ out, int n_rows) {
    __shared__ uint32_t As[128 * SPAD];
    __shared__ uint32_t Bs[128 * SPAD];
    __shared__ float    sBias1[HIDDEN];
    __shared__ float    sBias2[HIDDEN];

    int tid  = threadIdx.x;
    int lane = tid & 31;
    int wid  = tid >> 5;
    int q    = lane & 3;
    int lg   = lane >> 2;
    int wm   = wid >> 2;           // 0..1
    int wn   = wid & 3;            // 0..3
    int Rw   = wm * 64;
    int Nw   = wn * 32;
    int row0 = blockIdx.x * 128;

    if (tid < HIDDEN) {
        sBias1[tid] = g_b1eff[tid];
        sBias2[tid] = b2[tid];
    }

    float c1[4][4][4];
    #pragma unroll
    for (int i = 0; i < 4; i++)
        #pragma unroll
        for (int j = 0; j < 4; j++)
            #pragma unroll
            for (int t = 0; t < 4; t++) c1[i][j][t] = 0.0f;

    // ---------------- phase 1: h = relu([A0|A1] @ W1 + b1eff) ----------------
    for (int k0 = 0; k0 < 256; k0 += 32) {
        const float* Asrc = (k0 >= HIDDEN) ? A1 : A0;
        int kb = (k0 >= HIDDEN) ? (k0 - HIDDEN) : k0;

        #pragma unroll
        for (int it = 0; it < 4; it++) {
            int idx = tid + it * 256;
            int row = idx >> 3;
            int t   = idx & 7;
            int grow = row0 + row;
            float4 v = (grow < n_rows)
                ? __ldg((const float4*)&Asrc[(size_t)grow * HIDDEN + kb + t * 4])
                : make_float4(0.f, 0.f, 0.f, 0.f);
            uint32_t* dst = &As[row * SPAD + t];
            dst[0]  = f2tf32(v.x);
            dst[8]  = f2tf32(v.y);
            dst[16] = f2tf32(v.z);
            dst[24] = f2tf32(v.w);
        }
        {
            int n    = tid & 127;
            int koff = (tid >> 7) * 16;
            #pragma unroll
            for (int u = 0; u < 16; u++) {
                int k = koff + u;
                float bv = __ldg(&W1[(size_t)(k0 + k) * HIDDEN + n]);
                Bs[n * SPAD + (k & 3) * 8 + (k >> 2)] = f2tf32(bv);
            }
        }
        __syncthreads();

        #pragma unroll
        for (int s = 0; s < 4; s++) {
            uint32_t a[4][4];
            #pragma unroll
            for (int mt = 0; mt < 4; mt++) {
                int r = Rw + mt * 16 + lg;
                int o0 = r * SPAD + q * 8 + 2 * s;
                int o1 = (r + 8) * SPAD + q * 8 + 2 * s;
                a[mt][0] = As[o0]; a[mt][2] = As[o0 + 1];
                a[mt][1] = As[o1]; a[mt][3] = As[o1 + 1];
            }
            uint32_t b[4][2];
            #pragma unroll
            for (int nt = 0; nt < 4; nt++) {
                int ob = (Nw + nt * 8 + lg) * SPAD + q * 8 + 2 * s;
                b[nt][0] = Bs[ob]; b[nt][1] = Bs[ob + 1];
            }
            #pragma unroll
            for (int mt = 0; mt < 4; mt++)
                #pragma unroll
                for (int nt = 0; nt < 4; nt++)
                    asm volatile(
                        "mma.sync.aligned.m16n8k8.row.col.f32.tf32.tf32.f32 "
                        "{%0,%1,%2,%3}, {%4,%5,%6,%7}, {%8,%9}, {%0,%1,%2,%3};"
                        : "+f"(c1[mt][nt][0]), "+f"(c1[mt][nt][1]),
                          "+f"(c1[mt][nt][2]), "+f"(c1[mt][nt][3])
                        : "r"(a[mt][0]), "r"(a[mt][1]),
                          "r"(a[mt][2]), "r"(a[mt][3]),
                          "r"(b[nt][0]), "r"(b[nt][1]));
        }
        __syncthreads();
    }

    // ---------------- phase 2: x = h @ W2 + b2 -------------------------------
    float c2[4][4][4];
    #pragma unroll
    for (int i = 0; i < 4; i++)
        #pragma unroll
        for (int j = 0; j < 4; j++)
            #pragma unroll
            for (int t = 0; t < 4; t++) c2[i][j][t] = 0.0f;

    for (int s = 0; s < 4; s++) {        // k-tile s covers h cols 32s..32s+31
        // warps owning those h columns (wn == s) store them (bias+relu+tf32)
        if (wn == s) {
            #pragma unroll
            for (int mt = 0; mt < 4; mt++) {
                int r0 = Rw + mt * 16 + lg;
                int r1 = r0 + 8;
                #pragma unroll
                for (int nt = 0; nt < 4; nt++) {
                    int col = Nw + nt * 8 + 2 * q;      // global h col
                    int lk0 = nt * 8 + 2 * q;           // local k in tile
                    float bb0 = sBias1[col], bb1 = sBias1[col + 1];
                    float v0 = fmaxf(c1[mt][nt][0] + bb0, 0.f);
                    float v1 = fmaxf(c1[mt][nt][1] + bb1, 0.f);
                    float v2 = fmaxf(c1[mt][nt][2] + bb0, 0.f);
                    float v3 = fmaxf(c1[mt][nt][3] + bb1, 0.f);
                    int p0 = (lk0 & 3) * 8 + (lk0 >> 2);
                    int p1 = ((lk0 + 1) & 3) * 8 + ((lk0 + 1) >> 2);
                    As[r0 * SPAD + p0] = f2tf32(v0);
                    As[r0 * SPAD + p1] = f2tf32(v1);
                    As[r1 * SPAD + p0] = f2tf32(v2);
                    As[r1 * SPAD + p1] = f2tf32(v3);
                }
            }
        }
        // stage W2 k-tile s
        {
            int n    = tid & 127;
            int koff = (tid >> 7) * 16;
            int k0   = s * 32;
            #pragma unroll
            for (int u = 0; u < 16; u++) {
                int k = koff + u;
                float bv = __ldg(&W2[(size_t)(k0 + k) * HIDDEN + n]);
                Bs[n * SPAD + (k & 3) * 8 + (k >> 2)] = f2tf32(bv);
            }
        }
        __syncthreads();

        #pragma unroll
        for (int ss = 0; ss < 4; ss++) {
            uint32_t a[4][4];
            #pragma unroll
            for (int mt = 0; mt < 4; mt++) {
                int r = Rw + mt * 16 + lg;
                int o0 = r * SPAD + q * 8 + 2 * ss;
                int o1 = (r + 8) * SPAD + q * 8 + 2 * ss;
                a[mt][0] = As[o0]; a[mt][2] = As[o0 + 1];
                a[mt][1] = As[o1]; a[mt][3] = As[o1 + 1];
            }
            uint32_t b[4][2];
            #pragma unroll
            for (int nt = 0; nt < 4; nt++) {
                int ob = (Nw + nt * 8 + lg) * SPAD + q * 8 + 2 * ss;
                b[nt][0] = Bs[ob]; b[nt][1] = Bs[ob + 1];
            }
            #pragma unroll
            for (int mt = 0; mt < 4; mt++)
                #pragma unroll
                for (int nt = 0; nt < 4; nt++)
                    asm volatile(
                        "mma.sync.aligned.m16n8k8.row.col.f32.tf32.tf32.f32 "
                        "{%0,%1,%2,%3}, {%4,%5,%6,%7}, {%8,%9}, {%0,%1,%2,%3};"
                        : "+f"(c2[mt][nt][0]), "+f"(c2[mt][nt][1]),
                          "+f"(c2[mt][nt][2]), "+f"(c2[mt][nt][3])
                        : "r"(a[mt][0]), "r"(a[mt][1]),
                          "r"(a[mt][2]), "r"(a[mt][3]),
                          "r"(b[nt][0]), "r"(b[nt][1]));
        }
        __syncthreads();
    }

    // epilogue: x = c2 + b2
    #pragma unroll
    for (int mt = 0; mt < 4; mt++) {
        int r0g = row0 + Rw + mt * 16 + lg;
        int r1g = r0g + 8;
        #pragma unroll
        for (int nt = 0; nt < 4; nt++) {
            int col = Nw + nt * 8 + 2 * q;
            float bb0 = sBias2[col], bb1 = sBias2[col + 1];
            if (r0g < n_rows)
                *(float2*)&out[(size_t)r0g * HIDDEN + col] =
                    make_float2(c2[mt][nt][0] + bb0, c2[mt][nt][1] + bb1);
            if (r1g < n_rows)
                *(float2*)&out[(size_t)r1g * HIDDEN + col] =
                    make_float2(c2[mt][nt][2] + bb0, c2[mt][nt][3] + bb1);
        }
    }
}

// ---------------- launcher ---------------------------------------------------
extern "C" void kernel_launch(void* const* d_in, const int* in_sizes, int n_in,
                              void* d_out, int out_size) {
    const float* node_attr  = (const float*)d_in[0];
    const void*  edge_index = d_in[1];
    const float* edge_attr  = (const float*)d_in[2];
    const float* W1         = (const float*)d_in[3];
    const float* b1         = (const float*)d_in[4];
    const float* W2         = (const float*)d_in[5];
    const float* b2         = (const float*)d_in[6];

    int n_nodes = in_sizes[0] / HIDDEN;
    int n_edges = in_sizes[1] / 2;

    size_t x_el  = (size_t)n_nodes * HIDDEN;
    size_t ei_el = 2 * (size_t)n_edges;
    size_t ea_el = (size_t)n_edges * HIDDEN;

    float* out   = (float*)d_out;
    float* out_x = out;

    size_t os = (size_t)out_size;
    bool idx64 = false;
    float*     out_ei_f   = nullptr;
    long long* out_ei_raw = nullptr;
    float*     out_ea     = nullptr;
    if (os == x_el + ei_el + ea_el) {
        idx64 = false;
        out_ei_f = out + x_el;
        out_ea   = out + x_el + ei_el;
    } else if (os == x_el + 2 * ei_el + ea_el) {
        idx64 = true;
        out_ei_raw = (long long*)(out + x_el);
        out_ea     = out + x_el + 2 * ei_el;
    }

    float* d_agg; cudaGetSymbolAddress((void**)&d_agg, g_agg);

    // 1. zero agg + colsum
    {
        size_t total = (size_t)n_nodes * HIDDEN;
        int blocks = (int)((total + 511) / 512);
        if (blocks > 4096) blocks = 4096;
        zero_kernel<<<blocks, 512>>>(n_nodes);
    }

    // 2. scatter + edge_attr copy + colsum
    {
        int blocks = 2048;
        if (idx64) {
            const long long* recv = (const long long*)edge_index + n_edges;
            scatter_copy_kernel<long long><<<blocks, 256>>>(
                (const float4*)edge_attr, recv, (float4*)out_ea, n_edges);
        } else {
            const int* recv = (const int*)edge_index + n_edges;
            scatter_copy_kernel<int><<<blocks, 256>>>(
                (const float4*)edge_attr, recv, (float4*)out_ea, n_edges);
        }
    }

    // 3. edge_index passthrough
    if (out_ei_f) {
        int n = 2 * n_edges;
        ei_copy_i32_as_float_kernel<<<(n + 255) / 256, 256>>>(
            (const int*)edge_index, out_ei_f, n);
    } else if (out_ei_raw) {
        int n = 2 * n_edges;
        ei_copy_raw64_kernel<<<(n + 255) / 256, 256>>>(
            (const long long*)edge_index, out_ei_raw, n);
    }

    // 4. fold column means into bias (parallel)
    b1eff_kernel<<<HIDDEN, HIDDEN>>>(W1, b1, n_nodes);

    // 5. fused MLP: x = relu([node|agg]@W1 + b1eff) @ W2 + b2
    {
        int blocks = (n_nodes + 127) / 128;
        fused_mlp_kernel<<<blocks, 256>>>(node_attr, d_agg, W1, W2, b2,
                                          out_x, n_nodes);
    }
}

// round 6
// speedup vs baseline: 1.5805x; 1.0559x over previous
#include <cuda_runtime.h>
#include <cuda_bf16.h>
#include <cstdint>

#define HIDDEN 128
#define MAX_NODES 50048
#define MAX_EDGES 800000

// ---------------- scratch (static device globals; no allocation) -------------
__device__ float    g_agg[(size_t)MAX_NODES * HIDDEN];
__device__ float    g_colsum[HIDDEN];
__device__ float    g_b1eff[HIDDEN];
__device__ uint32_t g_W1t[8 * 4096];   // W1 tf32, transposed+permuted, 8 k-tiles
__device__ uint32_t g_W2t[4 * 4096];   // W2 tf32, same, 4 k-tiles

// ---------------- kernel 1: zero agg + colsum -------------------------------
__global__ void zero_kernel(int n_nodes) {
    size_t total = (size_t)n_nodes * HIDDEN;
    size_t i = (size_t)blockIdx.x * blockDim.x + threadIdx.x;
    size_t stride = (size_t)gridDim.x * blockDim.x;
    for (size_t idx = i; idx < total; idx += stride) g_agg[idx] = 0.0f;
    if (i < HIDDEN) g_colsum[i] = 0.0f;
}

// ---------------- kernel 2: scatter-add + edge_attr copy + colsum ------------
template<typename IDX>
__global__ void scatter_copy_kernel(const float4* __restrict__ ea,
                                    const IDX* __restrict__ recv,
                                    float4* __restrict__ out_ea,
                                    int n_edges) {
    int wl   = threadIdx.x >> 5;
    int lane = threadIdx.x & 31;
    int gw   = blockIdx.x * 8 + wl;
    int nW   = gridDim.x * 8;

    float4 acc = make_float4(0.f, 0.f, 0.f, 0.f);
    for (int e = gw; e < n_edges; e += nW) {
        int r = (int)__ldg(&recv[e]);
        float4 v = __ldg(&ea[(size_t)e * 32 + lane]);
        if (out_ea) out_ea[(size_t)e * 32 + lane] = v;
        acc.x += v.x; acc.y += v.y; acc.z += v.z; acc.w += v.w;
        float* dst = g_agg + (size_t)r * HIDDEN + lane * 4;
        asm volatile("red.global.add.v4.f32 [%0], {%1,%2,%3,%4};"
                     :: "l"(dst), "f"(v.x), "f"(v.y), "f"(v.z), "f"(v.w)
                     : "memory");
    }

    __shared__ float4 reds[8][32];
    reds[wl][lane] = acc;
    __syncthreads();
    if (wl == 0) {
        float4 s = reds[0][lane];
        #pragma unroll
        for (int w = 1; w < 8; w++) {
            float4 t = reds[w][lane];
            s.x += t.x; s.y += t.y; s.z += t.z; s.w += t.w;
        }
        atomicAdd(&g_colsum[lane * 4 + 0], s.x);
        atomicAdd(&g_colsum[lane * 4 + 1], s.y);
        atomicAdd(&g_colsum[lane * 4 + 2], s.z);
        atomicAdd(&g_colsum[lane * 4 + 3], s.w);
    }
}

// ---------------- kernel 3: edge_index passthrough ---------------------------
__global__ void ei_copy_i32_as_float_kernel(const int* __restrict__ ei,
                                            float* __restrict__ out, int n) {
    int i = blockIdx.x * blockDim.x + threadIdx.x;
    if (i < n) out[i] = (float)ei[i];
}
__global__ void ei_copy_raw64_kernel(const long long* __restrict__ ei,
                                     long long* __restrict__ out, int n) {
    int i = blockIdx.x * blockDim.x + threadIdx.x;
    if (i < n) out[i] = ei[i];
}

// ---------------- kernel 4: fold mean into bias (parallel) -------------------
__global__ void b1eff_kernel(const float* __restrict__ W1,
                             const float* __restrict__ b1, int n_nodes) {
    int j = blockIdx.x;
    int k = threadIdx.x;
    float inv = 1.0f / (float)n_nodes;
    float v = g_colsum[k] * inv * __ldg(&W1[(size_t)(HIDDEN + k) * HIDDEN + j]);
    #pragma unroll
    for (int o = 16; o > 0; o >>= 1) v += __shfl_down_sync(0xffffffffu, v, o);
    __shared__ float red[4];
    if ((k & 31) == 0) red[k >> 5] = v;
    __syncthreads();
    if (k == 0)
        g_b1eff[j] = b1[j] - (red[0] + red[1] + red[2] + red[3]);
}

// ---------------- weight pre-convert -----------------------------------------
// tile t of W (k0 = 32t): out[t*4096 + n*32 + p(k)] = tf32(W[(k0+k)*128 + n])
// p(k) = (k&3)*8 + (k>>2);  inverse: k = (pk&7)*4 + (pk>>3)
__device__ __forceinline__ uint32_t f2tf32(float f) {
    uint32_t u;
    asm("cvt.rna.tf32.f32 %0, %1;" : "=r"(u) : "f"(f));
    return u;
}

__global__ void wconv_kernel(const float* __restrict__ W,
                             uint32_t* __restrict__ out) {
    int t   = blockIdx.x;
    int tid = threadIdx.x;            // 256
    #pragma unroll
    for (int j = 0; j < 16; j++) {
        int o  = j * 256 + tid;       // 0..4095, coalesced writes
        int n  = o >> 5;
        int pk = o & 31;
        int k  = (pk & 7) * 4 + (pk >> 3);
        out[t * 4096 + o] = f2tf32(__ldg(&W[(size_t)(t * 32 + k) * HIDDEN + n]));
    }
}

// ---------------- fused 2-layer tf32 MLP, prefetched, pre-converted W --------
// 256 threads = 8 warps (2 M x 4 N), block tile 128x128, warp tile 64x32.
// Dynamic smem arena (words):
//   [0, 18944)        : Hs[4] h k-tile buffers, 4736 words each (SPAD=37)
//                       (phase 1 aliases Hs[0]=As staging, Hs[1]=Bs staging)
//   [18944, 23680)    : Bs2, W2 k-tile buffer
//   [23680, 23808)    : bias1 ; [23808, 23936) : bias2
#define SPAD 37
#define HS_W 4736
#define ARENA_WORDS 23936

__global__ void __launch_bounds__(256)
fused_mlp_kernel(const float* __restrict__ A0,
                 const float* __restrict__ A1,
                 const float* __restrict__ b2,
                 float* __restrict__ out, int n_rows) {
    extern __shared__ uint32_t sm[];
    uint32_t* Hs    = sm;                 // 4 buffers
    uint32_t* As    = sm;                 // phase-1 alias
    uint32_t* Bs    = sm + HS_W;          // phase-1 alias
    uint32_t* Bs2   = sm + 4 * HS_W;
    float*    sB1   = (float*)(sm + 23680);
    float*    sB2   = (float*)(sm + 23808);

    int tid  = threadIdx.x;
    int lane = tid & 31;
    int wid  = tid >> 5;
    int q    = lane & 3;
    int lg   = lane >> 2;
    int wm   = wid >> 2;
    int wn   = wid & 3;
    int Rw   = wm * 64;
    int Nw   = wn * 32;
    int row0 = blockIdx.x * 128;

    if (tid < HIDDEN) {
        sB1[tid] = g_b1eff[tid];
        sB2[tid] = b2[tid];
    }

    float c1[4][4][4];
    #pragma unroll
    for (int i = 0; i < 4; i++)
        #pragma unroll
        for (int j = 0; j < 4; j++)
            #pragma unroll
            for (int t = 0; t < 4; t++) c1[i][j][t] = 0.0f;

    // register prefetch buffers
    float4 ar[4];
    uint4  br[4];

    // load tile 0
    {
        #pragma unroll
        for (int it = 0; it < 4; it++) {
            int idx = tid + it * 256;
            int row = idx >> 3, tt = idx & 7;
            int grow = row0 + row;
            ar[it] = (grow < n_rows)
                ? __ldg((const float4*)&A0[(size_t)grow * HIDDEN + tt * 4])
                : make_float4(0.f, 0.f, 0.f, 0.f);
        }
        const uint4* src = (const uint4*)g_W1t;
        #pragma unroll
        for (int j = 0; j < 4; j++) br[j] = __ldg(&src[j * 256 + tid]);
    }

    // ---------------- phase 1: c1 = [A0|A1] @ W1 -----------------------------
    for (int t = 0; t < 8; t++) {
        // store prefetched tile to smem
        #pragma unroll
        for (int it = 0; it < 4; it++) {
            int idx = tid + it * 256;
            int row = idx >> 3, tt = idx & 7;
            uint32_t* dst = &As[row * SPAD + tt];
            dst[0]  = f2tf32(ar[it].x);
            dst[8]  = f2tf32(ar[it].y);
            dst[16] = f2tf32(ar[it].z);
            dst[24] = f2tf32(ar[it].w);
        }
        #pragma unroll
        for (int j = 0; j < 4; j++) {
            int o  = (j * 256 + tid) * 4;
            int n  = o >> 5;
            int pk = o & 31;
            uint32_t* dst = &Bs[n * SPAD + pk];
            dst[0] = br[j].x; dst[1] = br[j].y;
            dst[2] = br[j].z; dst[3] = br[j].w;
        }
        __syncthreads();

        // prefetch tile t+1
        if (t < 7) {
            const float* Asrc = (t + 1 >= 4) ? A1 : A0;
            int kb = ((t + 1) & 3) * 32;
            #pragma unroll
            for (int it = 0; it < 4; it++) {
                int idx = tid + it * 256;
                int row = idx >> 3, tt = idx & 7;
                int grow = row0 + row;
                ar[it] = (grow < n_rows)
                    ? __ldg((const float4*)&Asrc[(size_t)grow * HIDDEN + kb + tt * 4])
                    : make_float4(0.f, 0.f, 0.f, 0.f);
            }
            const uint4* src = (const uint4*)&g_W1t[(t + 1) * 4096];
            #pragma unroll
            for (int j = 0; j < 4; j++) br[j] = __ldg(&src[j * 256 + tid]);
        }

        #pragma unroll
        for (int s = 0; s < 4; s++) {
            uint32_t a[4][4];
            #pragma unroll
            for (int mt = 0; mt < 4; mt++) {
                int r = Rw + mt * 16 + lg;
                int o0 = r * SPAD + q * 8 + 2 * s;
                int o1 = (r + 8) * SPAD + q * 8 + 2 * s;
                a[mt][0] = As[o0]; a[mt][2] = As[o0 + 1];
                a[mt][1] = As[o1]; a[mt][3] = As[o1 + 1];
            }
            uint32_t b[4][2];
            #pragma unroll
            for (int nt = 0; nt < 4; nt++) {
                int ob = (Nw + nt * 8 + lg) * SPAD + q * 8 + 2 * s;
                b[nt][0] = Bs[ob]; b[nt][1] = Bs[ob + 1];
            }
            #pragma unroll
            for (int mt = 0; mt < 4; mt++)
                #pragma unroll
                for (int nt = 0; nt < 4; nt++)
                    asm volatile(
                        "mma.sync.aligned.m16n8k8.row.col.f32.tf32.tf32.f32 "
                        "{%0,%1,%2,%3}, {%4,%5,%6,%7}, {%8,%9}, {%0,%1,%2,%3};"
                        : "+f"(c1[mt][nt][0]), "+f"(c1[mt][nt][1]),
                          "+f"(c1[mt][nt][2]), "+f"(c1[mt][nt][3])
                        : "r"(a[mt][0]), "r"(a[mt][1]),
                          "r"(a[mt][2]), "r"(a[mt][3]),
                          "r"(b[nt][0]), "r"(b[nt][1]));
        }
        __syncthreads();
    }

    // ---------------- phase 2: x = relu(c1 + b1eff) @ W2 + b2 ----------------
    // stage ALL of h: warp (wm,wn) -> Hs[wn], rows Rw..Rw+63, cols Nw..Nw+31
    #pragma unroll
    for (int mt = 0; mt < 4; mt++) {
        int r0 = Rw + mt * 16 + lg;
        int r1 = r0 + 8;
        #pragma unroll
        for (int nt = 0; nt < 4; nt++) {
            int col = Nw + nt * 8 + 2 * q;
            int lk0 = nt * 8 + 2 * q;
            float bb0 = sB1[col], bb1 = sB1[col + 1];
            float v0 = fmaxf(c1[mt][nt][0] + bb0, 0.f);
            float v1 = fmaxf(c1[mt][nt][1] + bb1, 0.f);
            float v2 = fmaxf(c1[mt][nt][2] + bb0, 0.f);
            float v3 = fmaxf(c1[mt][nt][3] + bb1, 0.f);
            int p0 = (lk0 & 3) * 8 + (lk0 >> 2);
            int p1 = ((lk0 + 1) & 3) * 8 + ((lk0 + 1) >> 2);
            uint32_t* hb = &Hs[wn * HS_W];
            hb[r0 * SPAD + p0] = f2tf32(v0);
            hb[r0 * SPAD + p1] = f2tf32(v1);
            hb[r1 * SPAD + p0] = f2tf32(v2);
            hb[r1 * SPAD + p1] = f2tf32(v3);
        }
    }

    float c2[4][4][4];
    #pragma unroll
    for (int i = 0; i < 4; i++)
        #pragma unroll
        for (int j = 0; j < 4; j++)
            #pragma unroll
            for (int t = 0; t < 4; t++) c2[i][j][t] = 0.0f;

    // prefetch W2 tile 0
    {
        const uint4* src = (const uint4*)g_W2t;
        #pragma unroll
        for (int j = 0; j < 4; j++) br[j] = __ldg(&src[j * 256 + tid]);
    }

    for (int s = 0; s < 4; s++) {
        #pragma unroll
        for (int j = 0; j < 4; j++) {
            int o  = (j * 256 + tid) * 4;
            int n  = o >> 5;
            int pk = o & 31;
            uint32_t* dst = &Bs2[n * SPAD + pk];
            dst[0] = br[j].x; dst[1] = br[j].y;
            dst[2] = br[j].z; dst[3] = br[j].w;
        }
        __syncthreads();   // also covers h staging before first iteration

        if (s < 3) {
            const uint4* src = (const uint4*)&g_W2t[(s + 1) * 4096];
            #pragma unroll
            for (int j = 0; j < 4; j++) br[j] = __ldg(&src[j * 256 + tid]);
        }

        const uint32_t* Hb = &Hs[s * HS_W];
        #pragma unroll
        for (int ss = 0; ss < 4; ss++) {
            uint32_t a[4][4];
            #pragma unroll
            for (int mt = 0; mt < 4; mt++) {
                int r = Rw + mt * 16 + lg;
                int o0 = r * SPAD + q * 8 + 2 * ss;
                int o1 = (r + 8) * SPAD + q * 8 + 2 * ss;
                a[mt][0] = Hb[o0]; a[mt][2] = Hb[o0 + 1];
                a[mt][1] = Hb[o1]; a[mt][3] = Hb[o1 + 1];
            }
            uint32_t b[4][2];
            #pragma unroll
            for (int nt = 0; nt < 4; nt++) {
                int ob = (Nw + nt * 8 + lg) * SPAD + q * 8 + 2 * ss;
                b[nt][0] = Bs2[ob]; b[nt][1] = Bs2[ob + 1];
            }
            #pragma unroll
            for (int mt = 0; mt < 4; mt++)
                #pragma unroll
                for (int nt = 0; nt < 4; nt++)
                    asm volatile(
                        "mma.sync.aligned.m16n8k8.row.col.f32.tf32.tf32.f32 "
                        "{%0,%1,%2,%3}, {%4,%5,%6,%7}, {%8,%9}, {%0,%1,%2,%3};"
                        : "+f"(c2[mt][nt][0]), "+f"(c2[mt][nt][1]),
                          "+f"(c2[mt][nt][2]), "+f"(c2[mt][nt][3])
                        : "r"(a[mt][0]), "r"(a[mt][1]),
                          "r"(a[mt][2]), "r"(a[mt][3]),
                          "r"(b[nt][0]), "r"(b[nt][1]));
        }
        __syncthreads();
    }

    // epilogue
    #pragma unroll
    for (int mt = 0; mt < 4; mt++) {
        int r0g = row0 + Rw + mt * 16 + lg;
        int r1g = r0g + 8;
        #pragma unroll
        for (int nt = 0; nt < 4; nt++) {
            int col = Nw + nt * 8 + 2 * q;
            float bb0 = sB2[col], bb1 = sB2[col + 1];
            if (r0g < n_rows)
                *(float2*)&out[(size_t)r0g * HIDDEN + col] =
                    make_float2(c2[mt][nt][0] + bb0, c2[mt][nt][1] + bb1);
            if (r1g < n_rows)
                *(float2*)&out[(size_t)r1g * HIDDEN + col] =
                    make_float2(c2[mt][nt][2] + bb0, c2[mt][nt][3] + bb1);
        }
    }
}

// ---------------- launcher ---------------------------------------------------
extern "C" void kernel_launch(void* const* d_in, const int* in_sizes, int n_in,
                              void* d_out, int out_size) {
    const float* node_attr  = (const float*)d_in[0];
    const void*  edge_index = d_in[1];
    const float* edge_attr  = (const float*)d_in[2];
    const float* W1         = (const float*)d_in[3];
    const float* b1         = (const float*)d_in[4];
    const float* W2         = (const float*)d_in[5];
    const float* b2         = (const float*)d_in[6];

    int n_nodes = in_sizes[0] / HIDDEN;
    int n_edges = in_sizes[1] / 2;

    size_t x_el  = (size_t)n_nodes * HIDDEN;
    size_t ei_el = 2 * (size_t)n_edges;
    size_t ea_el = (size_t)n_edges * HIDDEN;

    float* out   = (float*)d_out;
    float* out_x = out;

    size_t os = (size_t)out_size;
    bool idx64 = false;
    float*     out_ei_f   = nullptr;
    long long* out_ei_raw = nullptr;
    float*     out_ea     = nullptr;
    if (os == x_el + ei_el + ea_el) {
        idx64 = false;
        out_ei_f = out + x_el;
        out_ea   = out + x_el + ei_el;
    } else if (os == x_el + 2 * ei_el + ea_el) {
        idx64 = true;
        out_ei_raw = (long long*)(out + x_el);
        out_ea     = out + x_el + 2 * ei_el;
    }

    float*    d_agg;  cudaGetSymbolAddress((void**)&d_agg, g_agg);
    uint32_t* d_W1t;  cudaGetSymbolAddress((void**)&d_W1t, g_W1t);
    uint32_t* d_W2t;  cudaGetSymbolAddress((void**)&d_W2t, g_W2t);

    // 1. zero agg + colsum
    {
        size_t total = (size_t)n_nodes * HIDDEN;
        int blocks = (int)((total + 511) / 512);
        if (blocks > 4096) blocks = 4096;
        zero_kernel<<<blocks, 512>>>(n_nodes);
    }

    // 1b. pre-convert weights (independent of scatter)
    wconv_kernel<<<8, 256>>>(W1, d_W1t);
    wconv_kernel<<<4, 256>>>(W2, d_W2t);

    // 2. scatter + edge_attr copy + colsum
    {
        int blocks = 2048;
        if (idx64) {
            const long long* recv = (const long long*)edge_index + n_edges;
            scatter_copy_kernel<long long><<<blocks, 256>>>(
                (const float4*)edge_attr, recv, (float4*)out_ea, n_edges);
        } else {
            const int* recv = (const int*)edge_index + n_edges;
            scatter_copy_kernel<int><<<blocks, 256>>>(
                (const float4*)edge_attr, recv, (float4*)out_ea, n_edges);
        }
    }

    // 3. edge_index passthrough
    if (out_ei_f) {
        int n = 2 * n_edges;
        ei_copy_i32_as_float_kernel<<<(n + 255) / 256, 256>>>(
            (const int*)edge_index, out_ei_f, n);
    } else if (out_ei_raw) {
        int n = 2 * n_edges;
        ei_copy_raw64_kernel<<<(n + 255) / 256, 256>>>(
            (const long long*)edge_index, out_ei_raw, n);
    }

    // 4. fold column means into bias
    b1eff_kernel<<<HIDDEN, HIDDEN>>>(W1, b1, n_nodes);

    // 5. fused MLP
    {
        int smem_bytes = ARENA_WORDS * 4;
        cudaFuncSetAttribute(fused_mlp_kernel,
                             cudaFuncAttributeMaxDynamicSharedMemorySize,
                             smem_bytes);
        int blocks = (n_nodes + 127) / 128;
        fused_mlp_kernel<<<blocks, 256, smem_bytes>>>(node_attr, d_agg, b2,
                                                      out_x, n_nodes);
    }
}

// round 7
// speedup vs baseline: 1.7228x; 1.0901x over previous
#include <cuda_runtime.h>
#include <cuda_bf16.h>
#include <cstdint>

#define HIDDEN 128
#define MAX_NODES 50048
#define MAX_EDGES 800000

// ---------------- scratch (static device globals; no allocation) -------------
__device__ float    g_agg[(size_t)MAX_NODES * HIDDEN];
__device__ float    g_colsum[HIDDEN];
__device__ float    g_b1eff[HIDDEN];
__device__ uint32_t g_W1t[8 * 4096];   // W1 tf32, transposed+permuted, 8 k-tiles
__device__ uint32_t g_W2t[4 * 4096];   // W2 tf32, same, 4 k-tiles

// ---------------- kernel 1: zero agg + colsum -------------------------------
__global__ void zero_kernel(int n_nodes) {
    size_t total = (size_t)n_nodes * HIDDEN;
    size_t i = (size_t)blockIdx.x * blockDim.x + threadIdx.x;
    size_t stride = (size_t)gridDim.x * blockDim.x;
    for (size_t idx = i; idx < total; idx += stride) g_agg[idx] = 0.0f;
    if (i < HIDDEN) g_colsum[i] = 0.0f;
}

// ---------------- kernel 2: scatter-add + edge_attr copy + colsum ------------
// Streaming (evict-first) hints on the copy path keep the 25.6 MB agg
// working set resident in L2 so red.add atomics stay on-die.
template<typename IDX>
__global__ void scatter_copy_kernel(const float4* __restrict__ ea,
                                    const IDX* __restrict__ recv,
                                    float4* __restrict__ out_ea,
                                    int n_edges) {
    int wl   = threadIdx.x >> 5;
    int lane = threadIdx.x & 31;
    int gw   = blockIdx.x * 8 + wl;
    int nW   = gridDim.x * 8;

    float4 acc = make_float4(0.f, 0.f, 0.f, 0.f);
    for (int e = gw; e < n_edges; e += nW) {
        int r = (int)__ldcs(&recv[e]);
        float4 v = __ldcs(&ea[(size_t)e * 32 + lane]);
        if (out_ea) __stcs(&out_ea[(size_t)e * 32 + lane], v);
        acc.x += v.x; acc.y += v.y; acc.z += v.z; acc.w += v.w;
        float* dst = g_agg + (size_t)r * HIDDEN + lane * 4;
        asm volatile("red.global.add.v4.f32 [%0], {%1,%2,%3,%4};"
                     :: "l"(dst), "f"(v.x), "f"(v.y), "f"(v.z), "f"(v.w)
                     : "memory");
    }

    __shared__ float4 reds[8][32];
    reds[wl][lane] = acc;
    __syncthreads();
    if (wl == 0) {
        float4 s = reds[0][lane];
        #pragma unroll
        for (int w = 1; w < 8; w++) {
            float4 t = reds[w][lane];
            s.x += t.x; s.y += t.y; s.z += t.z; s.w += t.w;
        }
        atomicAdd(&g_colsum[lane * 4 + 0], s.x);
        atomicAdd(&g_colsum[lane * 4 + 1], s.y);
        atomicAdd(&g_colsum[lane * 4 + 2], s.z);
        atomicAdd(&g_colsum[lane * 4 + 3], s.w);
    }
}

// ---------------- kernel 3: edge_index passthrough ---------------------------
__global__ void ei_copy_i32_as_float_kernel(const int* __restrict__ ei,
                                            float* __restrict__ out, int n) {
    int i = blockIdx.x * blockDim.x + threadIdx.x;
    if (i < n) __stcs(&out[i], (float)__ldcs(&ei[i]));
}
__global__ void ei_copy_raw64_kernel(const long long* __restrict__ ei,
                                     long long* __restrict__ out, int n) {
    int i = blockIdx.x * blockDim.x + threadIdx.x;
    if (i < n) __stcs(&out[i], __ldcs(&ei[i]));
}

// ---------------- kernel 4: fold mean into bias (parallel) -------------------
__global__ void b1eff_kernel(const float* __restrict__ W1,
                             const float* __restrict__ b1, int n_nodes) {
    int j = blockIdx.x;
    int k = threadIdx.x;
    float inv = 1.0f / (float)n_nodes;
    float v = g_colsum[k] * inv * __ldg(&W1[(size_t)(HIDDEN + k) * HIDDEN + j]);
    #pragma unroll
    for (int o = 16; o > 0; o >>= 1) v += __shfl_down_sync(0xffffffffu, v, o);
    __shared__ float red[4];
    if ((k & 31) == 0) red[k >> 5] = v;
    __syncthreads();
    if (k == 0)
        g_b1eff[j] = b1[j] - (red[0] + red[1] + red[2] + red[3]);
}

// ---------------- weight pre-convert -----------------------------------------
__device__ __forceinline__ uint32_t f2tf32(float f) {
    uint32_t u;
    asm("cvt.rna.tf32.f32 %0, %1;" : "=r"(u) : "f"(f));
    return u;
}

__global__ void wconv_kernel(const float* __restrict__ W,
                             uint32_t* __restrict__ out) {
    int t   = blockIdx.x;
    int tid = threadIdx.x;            // 256
    #pragma unroll
    for (int j = 0; j < 16; j++) {
        int o  = j * 256 + tid;
        int n  = o >> 5;
        int pk = o & 31;
        int k  = (pk & 7) * 4 + (pk >> 3);
        out[t * 4096 + o] = f2tf32(__ldg(&W[(size_t)(t * 32 + k) * HIDDEN + n]));
    }
}

// ---------------- fused 2-layer tf32 MLP -------------------------------------
#define SPAD 37
#define HS_W 4736
#define ARENA_WORDS 23936

__global__ void __launch_bounds__(256)
fused_mlp_kernel(const float* __restrict__ A0,
                 const float* __restrict__ A1,
                 const float* __restrict__ b2,
                 float* __restrict__ out, int n_rows) {
    extern __shared__ uint32_t sm[];
    uint32_t* Hs    = sm;
    uint32_t* As    = sm;
    uint32_t* Bs    = sm + HS_W;
    uint32_t* Bs2   = sm + 4 * HS_W;
    float*    sB1   = (float*)(sm + 23680);
    float*    sB2   = (float*)(sm + 23808);

    int tid  = threadIdx.x;
    int lane = tid & 31;
    int wid  = tid >> 5;
    int q    = lane & 3;
    int lg   = lane >> 2;
    int wm   = wid >> 2;
    int wn   = wid & 3;
    int Rw   = wm * 64;
    int Nw   = wn * 32;
    int row0 = blockIdx.x * 128;

    if (tid < HIDDEN) {
        sB1[tid] = g_b1eff[tid];
        sB2[tid] = b2[tid];
    }

    float c1[4][4][4];
    #pragma unroll
    for (int i = 0; i < 4; i++)
        #pragma unroll
        for (int j = 0; j < 4; j++)
            #pragma unroll
            for (int t = 0; t < 4; t++) c1[i][j][t] = 0.0f;

    float4 ar[4];
    uint4  br[4];

    {
        #pragma unroll
        for (int it = 0; it < 4; it++) {
            int idx = tid + it * 256;
            int row = idx >> 3, tt = idx & 7;
            int grow = row0 + row;
            ar[it] = (grow < n_rows)
                ? __ldg((const float4*)&A0[(size_t)grow * HIDDEN + tt * 4])
                : make_float4(0.f, 0.f, 0.f, 0.f);
        }
        const uint4* src = (const uint4*)g_W1t;
        #pragma unroll
        for (int j = 0; j < 4; j++) br[j] = __ldg(&src[j * 256 + tid]);
    }

    for (int t = 0; t < 8; t++) {
        #pragma unroll
        for (int it = 0; it < 4; it++) {
            int idx = tid + it * 256;
            int row = idx >> 3, tt = idx & 7;
            uint32_t* dst = &As[row * SPAD + tt];
            dst[0]  = f2tf32(ar[it].x);
            dst[8]  = f2tf32(ar[it].y);
            dst[16] = f2tf32(ar[it].z);
            dst[24] = f2tf32(ar[it].w);
        }
        #pragma unroll
        for (int j = 0; j < 4; j++) {
            int o  = (j * 256 + tid) * 4;
            int n  = o >> 5;
            int pk = o & 31;
            uint32_t* dst = &Bs[n * SPAD + pk];
            dst[0] = br[j].x; dst[1] = br[j].y;
            dst[2] = br[j].z; dst[3] = br[j].w;
        }
        __syncthreads();

        if (t < 7) {
            const float* Asrc = (t + 1 >= 4) ? A1 : A0;
            int kb = ((t + 1) & 3) * 32;
            #pragma unroll
            for (int it = 0; it < 4; it++) {
                int idx = tid + it * 256;
                int row = idx >> 3, tt = idx & 7;
                int grow = row0 + row;
                ar[it] = (grow < n_rows)
                    ? __ldg((const float4*)&Asrc[(size_t)grow * HIDDEN + kb + tt * 4])
                    : make_float4(0.f, 0.f, 0.f, 0.f);
            }
            const uint4* src = (const uint4*)&g_W1t[(t + 1) * 4096];
            #pragma unroll
            for (int j = 0; j < 4; j++) br[j] = __ldg(&src[j * 256 + tid]);
        }

        #pragma unroll
        for (int s = 0; s < 4; s++) {
            uint32_t a[4][4];
            #pragma unroll
            for (int mt = 0; mt < 4; mt++) {
                int r = Rw + mt * 16 + lg;
                int o0 = r * SPAD + q * 8 + 2 * s;
                int o1 = (r + 8) * SPAD + q * 8 + 2 * s;
                a[mt][0] = As[o0]; a[mt][2] = As[o0 + 1];
                a[mt][1] = As[o1]; a[mt][3] = As[o1 + 1];
            }
            uint32_t b[4][2];
            #pragma unroll
            for (int nt = 0; nt < 4; nt++) {
                int ob = (Nw + nt * 8 + lg) * SPAD + q * 8 + 2 * s;
                b[nt][0] = Bs[ob]; b[nt][1] = Bs[ob + 1];
            }
            #pragma unroll
            for (int mt = 0; mt < 4; mt++)
                #pragma unroll
                for (int nt = 0; nt < 4; nt++)
                    asm volatile(
                        "mma.sync.aligned.m16n8k8.row.col.f32.tf32.tf32.f32 "
                        "{%0,%1,%2,%3}, {%4,%5,%6,%7}, {%8,%9}, {%0,%1,%2,%3};"
                        : "+f"(c1[mt][nt][0]), "+f"(c1[mt][nt][1]),
                          "+f"(c1[mt][nt][2]), "+f"(c1[mt][nt][3])
                        : "r"(a[mt][0]), "r"(a[mt][1]),
                          "r"(a[mt][2]), "r"(a[mt][3]),
                          "r"(b[nt][0]), "r"(b[nt][1]));
        }
        __syncthreads();
    }

    // phase 2
    #pragma unroll
    for (int mt = 0; mt < 4; mt++) {
        int r0 = Rw + mt * 16 + lg;
        int r1 = r0 + 8;
        #pragma unroll
        for (int nt = 0; nt < 4; nt++) {
            int col = Nw + nt * 8 + 2 * q;
            int lk0 = nt * 8 + 2 * q;
            float bb0 = sB1[col], bb1 = sB1[col + 1];
            float v0 = fmaxf(c1[mt][nt][0] + bb0, 0.f);
            float v1 = fmaxf(c1[mt][nt][1] + bb1, 0.f);
            float v2 = fmaxf(c1[mt][nt][2] + bb0, 0.f);
            float v3 = fmaxf(c1[mt][nt][3] + bb1, 0.f);
            int p0 = (lk0 & 3) * 8 + (lk0 >> 2);
            int p1 = ((lk0 + 1) & 3) * 8 + ((lk0 + 1) >> 2);
            uint32_t* hb = &Hs[wn * HS_W];
            hb[r0 * SPAD + p0] = f2tf32(v0);
            hb[r0 * SPAD + p1] = f2tf32(v1);
            hb[r1 * SPAD + p0] = f2tf32(v2);
            hb[r1 * SPAD + p1] = f2tf32(v3);
        }
    }

    float c2[4][4][4];
    #pragma unroll
    for (int i = 0; i < 4; i++)
        #pragma unroll
        for (int j = 0; j < 4; j++)
            #pragma unroll
            for (int t = 0; t < 4; t++) c2[i][j][t] = 0.0f;

    {
        const uint4* src = (const uint4*)g_W2t;
        #pragma unroll
        for (int j = 0; j < 4; j++) br[j] = __ldg(&src[j * 256 + tid]);
    }

    for (int s = 0; s < 4; s++) {
        #pragma unroll
        for (int j = 0; j < 4; j++) {
            int o  = (j * 256 + tid) * 4;
            int n  = o >> 5;
            int pk = o & 31;
            uint32_t* dst = &Bs2[n * SPAD + pk];
            dst[0] = br[j].x; dst[1] = br[j].y;
            dst[2] = br[j].z; dst[3] = br[j].w;
        }
        __syncthreads();

        if (s < 3) {
            const uint4* src = (const uint4*)&g_W2t[(s + 1) * 4096];
            #pragma unroll
            for (int j = 0; j < 4; j++) br[j] = __ldg(&src[j * 256 + tid]);
        }

        const uint32_t* Hb = &Hs[s * HS_W];
        #pragma unroll
        for (int ss = 0; ss < 4; ss++) {
            uint32_t a[4][4];
            #pragma unroll
            for (int mt = 0; mt < 4; mt++) {
                int r = Rw + mt * 16 + lg;
                int o0 = r * SPAD + q * 8 + 2 * ss;
                int o1 = (r + 8) * SPAD + q * 8 + 2 * ss;
                a[mt][0] = Hb[o0]; a[mt][2] = Hb[o0 + 1];
                a[mt][1] = Hb[o1]; a[mt][3] = Hb[o1 + 1];
            }
            uint32_t b[4][2];
            #pragma unroll
            for (int nt = 0; nt < 4; nt++) {
                int ob = (Nw + nt * 8 + lg) * SPAD + q * 8 + 2 * ss;
                b[nt][0] = Bs2[ob]; b[nt][1] = Bs2[ob + 1];
            }
            #pragma unroll
            for (int mt = 0; mt < 4; mt++)
                #pragma unroll
                for (int nt = 0; nt < 4; nt++)
                    asm volatile(
                        "mma.sync.aligned.m16n8k8.row.col.f32.tf32.tf32.f32 "
                        "{%0,%1,%2,%3}, {%4,%5,%6,%7}, {%8,%9}, {%0,%1,%2,%3};"
                        : "+f"(c2[mt][nt][0]), "+f"(c2[mt][nt][1]),
                          "+f"(c2[mt][nt][2]), "+f"(c2[mt][nt][3])
                        : "r"(a[mt][0]), "r"(a[mt][1]),
                          "r"(a[mt][2]), "r"(a[mt][3]),
                          "r"(b[nt][0]), "r"(b[nt][1]));
        }
        __syncthreads();
    }

    #pragma unroll
    for (int mt = 0; mt < 4; mt++) {
        int r0g = row0 + Rw + mt * 16 + lg;
        int r1g = r0g + 8;
        #pragma unroll
        for (int nt = 0; nt < 4; nt++) {
            int col = Nw + nt * 8 + 2 * q;
            float bb0 = sB2[col], bb1 = sB2[col + 1];
            if (r0g < n_rows)
                *(float2*)&out[(size_t)r0g * HIDDEN + col] =
                    make_float2(c2[mt][nt][0] + bb0, c2[mt][nt][1] + bb1);
            if (r1g < n_rows)
                *(float2*)&out[(size_t)r1g * HIDDEN + col] =
                    make_float2(c2[mt][nt][2] + bb0, c2[mt][nt][3] + bb1);
        }
    }
}

// ---------------- launcher ---------------------------------------------------
extern "C" void kernel_launch(void* const* d_in, const int* in_sizes, int n_in,
                              void* d_out, int out_size) {
    const float* node_attr  = (const float*)d_in[0];
    const void*  edge_index = d_in[1];
    const float* edge_attr  = (const float*)d_in[2];
    const float* W1         = (const float*)d_in[3];
    const float* b1         = (const float*)d_in[4];
    const float* W2         = (const float*)d_in[5];
    const float* b2         = (const float*)d_in[6];

    int n_nodes = in_sizes[0] / HIDDEN;
    int n_edges = in_sizes[1] / 2;

    size_t x_el  = (size_t)n_nodes * HIDDEN;
    size_t ei_el = 2 * (size_t)n_edges;
    size_t ea_el = (size_t)n_edges * HIDDEN;

    float* out   = (float*)d_out;
    float* out_x = out;

    size_t os = (size_t)out_size;
    bool idx64 = false;
    float*     out_ei_f   = nullptr;
    long long* out_ei_raw = nullptr;
    float*     out_ea     = nullptr;
    if (os == x_el + ei_el + ea_el) {
        idx64 = false;
        out_ei_f = out + x_el;
        out_ea   = out + x_el + ei_el;
    } else if (os == x_el + 2 * ei_el + ea_el) {
        idx64 = true;
        out_ei_raw = (long long*)(out + x_el);
        out_ea     = out + x_el + 2 * ei_el;
    }

    float*    d_agg;  cudaGetSymbolAddress((void**)&d_agg, g_agg);
    uint32_t* d_W1t;  cudaGetSymbolAddress((void**)&d_W1t, g_W1t);
    uint32_t* d_W2t;  cudaGetSymbolAddress((void**)&d_W2t, g_W2t);

    // 1. zero agg + colsum
    {
        size_t total = (size_t)n_nodes * HIDDEN;
        int blocks = (int)((total + 511) / 512);
        if (blocks > 4096) blocks = 4096;
        zero_kernel<<<blocks, 512>>>(n_nodes);
    }

    // 1b. pre-convert weights
    wconv_kernel<<<8, 256>>>(W1, d_W1t);
    wconv_kernel<<<4, 256>>>(W2, d_W2t);

    // 2. scatter + edge_attr copy + colsum
    {
        int blocks = 2048;
        if (idx64) {
            const long long* recv = (const long long*)edge_index + n_edges;
            scatter_copy_kernel<long long><<<blocks, 256>>>(
                (const float4*)edge_attr, recv, (float4*)out_ea, n_edges);
        } else {
            const int* recv = (const int*)edge_index + n_edges;
            scatter_copy_kernel<int><<<blocks, 256>>>(
                (const float4*)edge_attr, recv, (float4*)out_ea, n_edges);
        }
    }

    // 3. edge_index passthrough
    if (out_ei_f) {
        int n = 2 * n_edges;
        ei_copy_i32_as_float_kernel<<<(n + 255) / 256, 256>>>(
            (const int*)edge_index, out_ei_f, n);
    } else if (out_ei_raw) {
        int n = 2 * n_edges;
        ei_copy_raw64_kernel<<<(n + 255) / 256, 256>>>(
            (const long long*)edge_index, out_ei_raw, n);
    }

    // 4. fold column means into bias
    b1eff_kernel<<<HIDDEN, HIDDEN>>>(W1, b1, n_nodes);

    // 5. fused MLP
    {
        int smem_bytes = ARENA_WORDS * 4;
        cudaFuncSetAttribute(fused_mlp_kernel,
                             cudaFuncAttributeMaxDynamicSharedMemorySize,
                             smem_bytes);
        int blocks = (n_nodes + 127) / 128;
        fused_mlp_kernel<<<blocks, 256, smem_bytes>>>(node_attr, d_agg, b2,
                                                      out_x, n_nodes);
    }
}

// round 8
// speedup vs baseline: 1.8845x; 1.0939x over previous
#include <cuda_runtime.h>
#include <cuda_bf16.h>
#include <cstdint>

#define HIDDEN 128
#define MAX_NODES 50048
#define MAX_EDGES 800000

// ---------------- scratch (static device globals; no allocation) -------------
__device__ float    g_agg[(size_t)MAX_NODES * HIDDEN];
__device__ float    g_colsum[HIDDEN];
__device__ float    g_b1eff[HIDDEN];
__device__ uint32_t g_W1t[8 * 4096];   // W1 tf32, transposed+permuted, 8 k-tiles
__device__ uint32_t g_W2t[4 * 4096];   // W2 tf32, same, 4 k-tiles

// ---------------- kernel 1: zero agg + colsum -------------------------------
__global__ void zero_kernel(int n_nodes) {
    size_t total = (size_t)n_nodes * HIDDEN;
    size_t i = (size_t)blockIdx.x * blockDim.x + threadIdx.x;
    size_t stride = (size_t)gridDim.x * blockDim.x;
    for (size_t idx = i; idx < total; idx += stride) g_agg[idx] = 0.0f;
    if (i < HIDDEN) g_colsum[i] = 0.0f;
}

// ---------------- kernel 2: scatter-add + edge_attr copy + colsum ------------
// x4 edge unroll: batch 4 independent index loads, 4 vector loads, 4 stores,
// 4 reductions per warp iteration -> MLP_eff ~4x, feeds DRAM/LTS properly.
// Streaming hints keep the 25.6 MB agg set resident in L2.
template<typename IDX>
__global__ void scatter_copy_kernel(const float4* __restrict__ ea,
                                    const IDX* __restrict__ recv,
                                    float4* __restrict__ out_ea,
                                    int n_edges) {
    int wl   = threadIdx.x >> 5;
    int lane = threadIdx.x & 31;
    int gw   = blockIdx.x * 8 + wl;
    int nW   = gridDim.x * 8;

    float4 acc = make_float4(0.f, 0.f, 0.f, 0.f);

    int e4_limit = n_edges & ~3;       // multiple of 4
    // main: 4 edges per iteration
    for (int e = gw * 4; e + 3 < e4_limit; e += nW * 4) {
        int r0 = (int)__ldcs(&recv[e + 0]);
        int r1 = (int)__ldcs(&recv[e + 1]);
        int r2 = (int)__ldcs(&recv[e + 2]);
        int r3 = (int)__ldcs(&recv[e + 3]);
        float4 v0 = __ldcs(&ea[(size_t)(e + 0) * 32 + lane]);
        float4 v1 = __ldcs(&ea[(size_t)(e + 1) * 32 + lane]);
        float4 v2 = __ldcs(&ea[(size_t)(e + 2) * 32 + lane]);
        float4 v3 = __ldcs(&ea[(size_t)(e + 3) * 32 + lane]);
        if (out_ea) {
            __stcs(&out_ea[(size_t)(e + 0) * 32 + lane], v0);
            __stcs(&out_ea[(size_t)(e + 1) * 32 + lane], v1);
            __stcs(&out_ea[(size_t)(e + 2) * 32 + lane], v2);
            __stcs(&out_ea[(size_t)(e + 3) * 32 + lane], v3);
        }
        acc.x += v0.x + v1.x + v2.x + v3.x;
        acc.y += v0.y + v1.y + v2.y + v3.y;
        acc.z += v0.z + v1.z + v2.z + v3.z;
        acc.w += v0.w + v1.w + v2.w + v3.w;
        float* d0 = g_agg + (size_t)r0 * HIDDEN + lane * 4;
        float* d1 = g_agg + (size_t)r1 * HIDDEN + lane * 4;
        float* d2 = g_agg + (size_t)r2 * HIDDEN + lane * 4;
        float* d3 = g_agg + (size_t)r3 * HIDDEN + lane * 4;
        asm volatile("red.global.add.v4.f32 [%0], {%1,%2,%3,%4};"
                     :: "l"(d0), "f"(v0.x), "f"(v0.y), "f"(v0.z), "f"(v0.w) : "memory");
        asm volatile("red.global.add.v4.f32 [%0], {%1,%2,%3,%4};"
                     :: "l"(d1), "f"(v1.x), "f"(v1.y), "f"(v1.z), "f"(v1.w) : "memory");
        asm volatile("red.global.add.v4.f32 [%0], {%1,%2,%3,%4};"
                     :: "l"(d2), "f"(v2.x), "f"(v2.y), "f"(v2.z), "f"(v2.w) : "memory");
        asm volatile("red.global.add.v4.f32 [%0], {%1,%2,%3,%4};"
                     :: "l"(d3), "f"(v3.x), "f"(v3.y), "f"(v3.z), "f"(v3.w) : "memory");
    }
    // tail
    for (int e = e4_limit + gw; e < n_edges; e += nW) {
        int r = (int)__ldcs(&recv[e]);
        float4 v = __ldcs(&ea[(size_t)e * 32 + lane]);
        if (out_ea) __stcs(&out_ea[(size_t)e * 32 + lane], v);
        acc.x += v.x; acc.y += v.y; acc.z += v.z; acc.w += v.w;
        float* dst = g_agg + (size_t)r * HIDDEN + lane * 4;
        asm volatile("red.global.add.v4.f32 [%0], {%1,%2,%3,%4};"
                     :: "l"(dst), "f"(v.x), "f"(v.y), "f"(v.z), "f"(v.w) : "memory");
    }

    __shared__ float4 reds[8][32];
    reds[wl][lane] = acc;
    __syncthreads();
    if (wl == 0) {
        float4 s = reds[0][lane];
        #pragma unroll
        for (int w = 1; w < 8; w++) {
            float4 t = reds[w][lane];
            s.x += t.x; s.y += t.y; s.z += t.z; s.w += t.w;
        }
        atomicAdd(&g_colsum[lane * 4 + 0], s.x);
        atomicAdd(&g_colsum[lane * 4 + 1], s.y);
        atomicAdd(&g_colsum[lane * 4 + 2], s.z);
        atomicAdd(&g_colsum[lane * 4 + 3], s.w);
    }
}

// ---------------- kernel 3: edge_index passthrough ---------------------------
__global__ void ei_copy_i32_as_float_kernel(const int* __restrict__ ei,
                                            float* __restrict__ out, int n) {
    int i = blockIdx.x * blockDim.x + threadIdx.x;
    if (i < n) __stcs(&out[i], (float)__ldcs(&ei[i]));
}
__global__ void ei_copy_raw64_kernel(const long long* __restrict__ ei,
                                     long long* __restrict__ out, int n) {
    int i = blockIdx.x * blockDim.x + threadIdx.x;
    if (i < n) __stcs(&out[i], __ldcs(&ei[i]));
}

// ---------------- kernel 4: fold mean into bias (parallel) -------------------
__global__ void b1eff_kernel(const float* __restrict__ W1,
                             const float* __restrict__ b1, int n_nodes) {
    int j = blockIdx.x;
    int k = threadIdx.x;
    float inv = 1.0f / (float)n_nodes;
    float v = g_colsum[k] * inv * __ldg(&W1[(size_t)(HIDDEN + k) * HIDDEN + j]);
    #pragma unroll
    for (int o = 16; o > 0; o >>= 1) v += __shfl_down_sync(0xffffffffu, v, o);
    __shared__ float red[4];
    if ((k & 31) == 0) red[k >> 5] = v;
    __syncthreads();
    if (k == 0)
        g_b1eff[j] = b1[j] - (red[0] + red[1] + red[2] + red[3]);
}

// ---------------- weight pre-convert -----------------------------------------
__device__ __forceinline__ uint32_t f2tf32(float f) {
    uint32_t u;
    asm("cvt.rna.tf32.f32 %0, %1;" : "=r"(u) : "f"(f));
    return u;
}

__global__ void wconv_kernel(const float* __restrict__ W,
                             uint32_t* __restrict__ out) {
    int t   = blockIdx.x;
    int tid = threadIdx.x;            // 256
    #pragma unroll
    for (int j = 0; j < 16; j++) {
        int o  = j * 256 + tid;
        int n  = o >> 5;
        int pk = o & 31;
        int k  = (pk & 7) * 4 + (pk >> 3);
        out[t * 4096 + o] = f2tf32(__ldg(&W[(size_t)(t * 32 + k) * HIDDEN + n]));
    }
}

// ---------------- fused 2-layer tf32 MLP -------------------------------------
#define SPAD 37
#define HS_W 4736
#define ARENA_WORDS 23936

__global__ void __launch_bounds__(256)
fused_mlp_kernel(const float* __restrict__ A0,
                 const float* __restrict__ A1,
                 const float* __restrict__ b2,
                 float* __restrict__ out, int n_rows) {
    extern __shared__ uint32_t sm[];
    uint32_t* Hs    = sm;
    uint32_t* As    = sm;
    uint32_t* Bs    = sm + HS_W;
    uint32_t* Bs2   = sm + 4 * HS_W;
    float*    sB1   = (float*)(sm + 23680);
    float*    sB2   = (float*)(sm + 23808);

    int tid  = threadIdx.x;
    int lane = tid & 31;
    int wid  = tid >> 5;
    int q    = lane & 3;
    int lg   = lane >> 2;
    int wm   = wid >> 2;
    int wn   = wid & 3;
    int Rw   = wm * 64;
    int Nw   = wn * 32;
    int row0 = blockIdx.x * 128;

    if (tid < HIDDEN) {
        sB1[tid] = g_b1eff[tid];
        sB2[tid] = b2[tid];
    }

    float c1[4][4][4];
    #pragma unroll
    for (int i = 0; i < 4; i++)
        #pragma unroll
        for (int j = 0; j < 4; j++)
            #pragma unroll
            for (int t = 0; t < 4; t++) c1[i][j][t] = 0.0f;

    float4 ar[4];
    uint4  br[4];

    {
        #pragma unroll
        for (int it = 0; it < 4; it++) {
            int idx = tid + it * 256;
            int row = idx >> 3, tt = idx & 7;
            int grow = row0 + row;
            ar[it] = (grow < n_rows)
                ? __ldg((const float4*)&A0[(size_t)grow * HIDDEN + tt * 4])
                : make_float4(0.f, 0.f, 0.f, 0.f);
        }
        const uint4* src = (const uint4*)g_W1t;
        #pragma unroll
        for (int j = 0; j < 4; j++) br[j] = __ldg(&src[j * 256 + tid]);
    }

    for (int t = 0; t < 8; t++) {
        #pragma unroll
        for (int it = 0; it < 4; it++) {
            int idx = tid + it * 256;
            int row = idx >> 3, tt = idx & 7;
            uint32_t* dst = &As[row * SPAD + tt];
            dst[0]  = f2tf32(ar[it].x);
            dst[8]  = f2tf32(ar[it].y);
            dst[16] = f2tf32(ar[it].z);
            dst[24] = f2tf32(ar[it].w);
        }
        #pragma unroll
        for (int j = 0; j < 4; j++) {
            int o  = (j * 256 + tid) * 4;
            int n  = o >> 5;
            int pk = o & 31;
            uint32_t* dst = &Bs[n * SPAD + pk];
            dst[0] = br[j].x; dst[1] = br[j].y;
            dst[2] = br[j].z; dst[3] = br[j].w;
        }
        __syncthreads();

        if (t < 7) {
            const float* Asrc = (t + 1 >= 4) ? A1 : A0;
            int kb = ((t + 1) & 3) * 32;
            #pragma unroll
            for (int it = 0; it < 4; it++) {
                int idx = tid + it * 256;
                int row = idx >> 3, tt = idx & 7;
                int grow = row0 + row;
                ar[it] = (grow < n_rows)
                    ? __ldg((const float4*)&Asrc[(size_t)grow * HIDDEN + kb + tt * 4])
                    : make_float4(0.f, 0.f, 0.f, 0.f);
            }
            const uint4* src = (const uint4*)&g_W1t[(t + 1) * 4096];
            #pragma unroll
            for (int j = 0; j < 4; j++) br[j] = __ldg(&src[j * 256 + tid]);
        }

        #pragma unroll
        for (int s = 0; s < 4; s++) {
            uint32_t a[4][4];
            #pragma unroll
            for (int mt = 0; mt < 4; mt++) {
                int r = Rw + mt * 16 + lg;
                int o0 = r * SPAD + q * 8 + 2 * s;
                int o1 = (r + 8) * SPAD + q * 8 + 2 * s;
                a[mt][0] = As[o0]; a[mt][2] = As[o0 + 1];
                a[mt][1] = As[o1]; a[mt][3] = As[o1 + 1];
            }
            uint32_t b[4][2];
            #pragma unroll
            for (int nt = 0; nt < 4; nt++) {
                int ob = (Nw + nt * 8 + lg) * SPAD + q * 8 + 2 * s;
                b[nt][0] = Bs[ob]; b[nt][1] = Bs[ob + 1];
            }
            #pragma unroll
            for (int mt = 0; mt < 4; mt++)
                #pragma unroll
                for (int nt = 0; nt < 4; nt++)
                    asm volatile(
                        "mma.sync.aligned.m16n8k8.row.col.f32.tf32.tf32.f32 "
                        "{%0,%1,%2,%3}, {%4,%5,%6,%7}, {%8,%9}, {%0,%1,%2,%3};"
                        : "+f"(c1[mt][nt][0]), "+f"(c1[mt][nt][1]),
                          "+f"(c1[mt][nt][2]), "+f"(c1[mt][nt][3])
                        : "r"(a[mt][0]), "r"(a[mt][1]),
                          "r"(a[mt][2]), "r"(a[mt][3]),
                          "r"(b[nt][0]), "r"(b[nt][1]));
        }
        __syncthreads();
    }

    // phase 2
    #pragma unroll
    for (int mt = 0; mt < 4; mt++) {
        int r0 = Rw + mt * 16 + lg;
        int r1 = r0 + 8;
        #pragma unroll
        for (int nt = 0; nt < 4; nt++) {
            int col = Nw + nt * 8 + 2 * q;
            int lk0 = nt * 8 + 2 * q;
            float bb0 = sB1[col], bb1 = sB1[col + 1];
            float v0 = fmaxf(c1[mt][nt][0] + bb0, 0.f);
            float v1 = fmaxf(c1[mt][nt][1] + bb1, 0.f);
            float v2 = fmaxf(c1[mt][nt][2] + bb0, 0.f);
            float v3 = fmaxf(c1[mt][nt][3] + bb1, 0.f);
            int p0 = (lk0 & 3) * 8 + (lk0 >> 2);
            int p1 = ((lk0 + 1) & 3) * 8 + ((lk0 + 1) >> 2);
            uint32_t* hb = &Hs[wn * HS_W];
            hb[r0 * SPAD + p0] = f2tf32(v0);
            hb[r0 * SPAD + p1] = f2tf32(v1);
            hb[r1 * SPAD + p0] = f2tf32(v2);
            hb[r1 * SPAD + p1] = f2tf32(v3);
        }
    }

    float c2[4][4][4];
    #pragma unroll
    for (int i = 0; i < 4; i++)
        #pragma unroll
        for (int j = 0; j < 4; j++)
            #pragma unroll
            for (int t = 0; t < 4; t++) c2[i][j][t] = 0.0f;

    {
        const uint4* src = (const uint4*)g_W2t;
        #pragma unroll
        for (int j = 0; j < 4; j++) br[j] = __ldg(&src[j * 256 + tid]);
    }

    for (int s = 0; s < 4; s++) {
        #pragma unroll
        for (int j = 0; j < 4; j++) {
            int o  = (j * 256 + tid) * 4;
            int n  = o >> 5;
            int pk = o & 31;
            uint32_t* dst = &Bs2[n * SPAD + pk];
            dst[0] = br[j].x; dst[1] = br[j].y;
            dst[2] = br[j].z; dst[3] = br[j].w;
        }
        __syncthreads();

        if (s < 3) {
            const uint4* src = (const uint4*)&g_W2t[(s + 1) * 4096];
            #pragma unroll
            for (int j = 0; j < 4; j++) br[j] = __ldg(&src[j * 256 + tid]);
        }

        const uint32_t* Hb = &Hs[s * HS_W];
        #pragma unroll
        for (int ss = 0; ss < 4; ss++) {
            uint32_t a[4][4];
            #pragma unroll
            for (int mt = 0; mt < 4; mt++) {
                int r = Rw + mt * 16 + lg;
                int o0 = r * SPAD + q * 8 + 2 * ss;
                int o1 = (r + 8) * SPAD + q * 8 + 2 * ss;
                a[mt][0] = Hb[o0]; a[mt][2] = Hb[o0 + 1];
                a[mt][1] = Hb[o1]; a[mt][3] = Hb[o1 + 1];
            }
            uint32_t b[4][2];
            #pragma unroll
            for (int nt = 0; nt < 4; nt++) {
                int ob = (Nw + nt * 8 + lg) * SPAD + q * 8 + 2 * ss;
                b[nt][0] = Bs2[ob]; b[nt][1] = Bs2[ob + 1];
            }
            #pragma unroll
            for (int mt = 0; mt < 4; mt++)
                #pragma unroll
                for (int nt = 0; nt < 4; nt++)
                    asm volatile(
                        "mma.sync.aligned.m16n8k8.row.col.f32.tf32.tf32.f32 "
                        "{%0,%1,%2,%3}, {%4,%5,%6,%7}, {%8,%9}, {%0,%1,%2,%3};"
                        : "+f"(c2[mt][nt][0]), "+f"(c2[mt][nt][1]),
                          "+f"(c2[mt][nt][2]), "+f"(c2[mt][nt][3])
                        : "r"(a[mt][0]), "r"(a[mt][1]),
                          "r"(a[mt][2]), "r"(a[mt][3]),
                          "r"(b[nt][0]), "r"(b[nt][1]));
        }
        __syncthreads();
    }

    #pragma unroll
    for (int mt = 0; mt < 4; mt++) {
        int r0g = row0 + Rw + mt * 16 + lg;
        int r1g = r0g + 8;
        #pragma unroll
        for (int nt = 0; nt < 4; nt++) {
            int col = Nw + nt * 8 + 2 * q;
            float bb0 = sB2[col], bb1 = sB2[col + 1];
            if (r0g < n_rows)
                *(float2*)&out[(size_t)r0g * HIDDEN + col] =
                    make_float2(c2[mt][nt][0] + bb0, c2[mt][nt][1] + bb1);
            if (r1g < n_rows)
                *(float2*)&out[(size_t)r1g * HIDDEN + col] =
                    make_float2(c2[mt][nt][2] + bb0, c2[mt][nt][3] + bb1);
        }
    }
}

// ---------------- launcher ---------------------------------------------------
extern "C" void kernel_launch(void* const* d_in, const int* in_sizes, int n_in,
                              void* d_out, int out_size) {
    const float* node_attr  = (const float*)d_in[0];
    const void*  edge_index = d_in[1];
    const float* edge_attr  = (const float*)d_in[2];
    const float* W1         = (const float*)d_in[3];
    const float* b1         = (const float*)d_in[4];
    const float* W2         = (const float*)d_in[5];
    const float* b2         = (const float*)d_in[6];

    int n_nodes = in_sizes[0] / HIDDEN;
    int n_edges = in_sizes[1] / 2;

    size_t x_el  = (size_t)n_nodes * HIDDEN;
    size_t ei_el = 2 * (size_t)n_edges;
    size_t ea_el = (size_t)n_edges * HIDDEN;

    float* out   = (float*)d_out;
    float* out_x = out;

    size_t os = (size_t)out_size;
    bool idx64 = false;
    float*     out_ei_f   = nullptr;
    long long* out_ei_raw = nullptr;
    float*     out_ea     = nullptr;
    if (os == x_el + ei_el + ea_el) {
        idx64 = false;
        out_ei_f = out + x_el;
        out_ea   = out + x_el + ei_el;
    } else if (os == x_el + 2 * ei_el + ea_el) {
        idx64 = true;
        out_ei_raw = (long long*)(out + x_el);
        out_ea     = out + x_el + 2 * ei_el;
    }

    float*    d_agg;  cudaGetSymbolAddress((void**)&d_agg, g_agg);
    uint32_t* d_W1t;  cudaGetSymbolAddress((void**)&d_W1t, g_W1t);
    uint32_t* d_W2t;  cudaGetSymbolAddress((void**)&d_W2t, g_W2t);

    // 1. zero agg + colsum
    {
        size_t total = (size_t)n_nodes * HIDDEN;
        int blocks = (int)((total + 511) / 512);
        if (blocks > 4096) blocks = 4096;
        zero_kernel<<<blocks, 512>>>(n_nodes);
    }

    // 1b. pre-convert weights
    wconv_kernel<<<8, 256>>>(W1, d_W1t);
    wconv_kernel<<<4, 256>>>(W2, d_W2t);

    // 2. scatter + edge_attr copy + colsum (x4 unrolled)
    {
        int blocks = 1184;   // 148 SMs x 8 blocks (one wave @ 256 thr)
        if (idx64) {
            const long long* recv = (const long long*)edge_index + n_edges;
            scatter_copy_kernel<long long><<<blocks, 256>>>(
                (const float4*)edge_attr, recv, (float4*)out_ea, n_edges);
        } else {
            const int* recv = (const int*)edge_index + n_edges;
            scatter_copy_kernel<int><<<blocks, 256>>>(
                (const float4*)edge_attr, recv, (float4*)out_ea, n_edges);
        }
    }

    // 3. edge_index passthrough
    if (out_ei_f) {
        int n = 2 * n_edges;
        ei_copy_i32_as_float_kernel<<<(n + 255) / 256, 256>>>(
            (const int*)edge_index, out_ei_f, n);
    } else if (out_ei_raw) {
        int n = 2 * n_edges;
        ei_copy_raw64_kernel<<<(n + 255) / 256, 256>>>(
            (const long long*)edge_index, out_ei_raw, n);
    }

    // 4. fold column means into bias
    b1eff_kernel<<<HIDDEN, HIDDEN>>>(W1, b1, n_nodes);

    // 5. fused MLP
    {
        int smem_bytes = ARENA_WORDS * 4;
        cudaFuncSetAttribute(fused_mlp_kernel,
                             cudaFuncAttributeMaxDynamicSharedMemorySize,
                             smem_bytes);
        int blocks = (n_nodes + 127) / 128;
        fused_mlp_kernel<<<blocks, 256, smem_bytes>>>(node_attr, d_agg, b2,
                                                      out_x, n_nodes);
    }
}